// round 1
// baseline (speedup 1.0000x reference)
#include <cuda_runtime.h>
#include <math.h>

#define S 2048
#define E 1024
#define NH 8
#define DH 128
#define BS 64
#define BT 32
#define QS_STRIDE 68   // [DH][QS_STRIDE], 16B-aligned rows-of-4 for float4 reads
#define KS_STRIDE 34   // [DH][KS_STRIDE], 8B-aligned pairs for float2 reads
#define PS_STRIDE 33   // [BS][PS_STRIDE]

// Scratch (allocation-free rule: __device__ globals)
__device__ float g_ig[NH * S];
__device__ float g_logf[NH * S];
__device__ float g_b[NH * S];     // inclusive cumsum of log_sigmoid(fg)
__device__ float g_a[NH * S];     // a[t] = ig[t] - b[t]
__device__ float g_M[NH * S];     // prefix max of a
__device__ float g_h[(size_t)S * E];

__device__ __forceinline__ float log_sigmoid_f(float x) {
    // -log(1+exp(-x)), numerically stable
    if (x >= 0.f) return -log1pf(expf(-x));
    return x - log1pf(expf(x));
}

// ---------------------------------------------------------------------------
// Kernel 1: gate projections. block = 8 warps, warp w -> head w, one s per block
// ig[h,s] = [q|k|v][s] . Wi[h] + bi[h];  logf = log_sigmoid([q|k|v][s].Wf[h]+bf[h])
// ---------------------------------------------------------------------------
__global__ __launch_bounds__(256) void gates_kernel(
    const float* __restrict__ q, const float* __restrict__ k,
    const float* __restrict__ v,
    const float* __restrict__ Wi, const float* __restrict__ bi,
    const float* __restrict__ Wf, const float* __restrict__ bf)
{
    int s = blockIdx.x;
    int w = threadIdx.x >> 5;
    int lane = threadIdx.x & 31;
    const float* qr = q + (size_t)s * E;
    const float* kr = k + (size_t)s * E;
    const float* vr = v + (size_t)s * E;
    const float* wi = Wi + (size_t)w * 3 * E;
    const float* wf = Wf + (size_t)w * 3 * E;
    float si = 0.f, sf = 0.f;
    for (int e = lane; e < E; e += 32) {
        float qe = qr[e], ke = kr[e], ve = vr[e];
        si += qe * wi[e] + ke * wi[E + e] + ve * wi[2 * E + e];
        sf += qe * wf[e] + ke * wf[E + e] + ve * wf[2 * E + e];
    }
#pragma unroll
    for (int o = 16; o > 0; o >>= 1) {
        si += __shfl_xor_sync(0xffffffffu, si, o);
        sf += __shfl_xor_sync(0xffffffffu, sf, o);
    }
    if (lane == 0) {
        g_ig[w * S + s] = si + bi[w];
        g_logf[w * S + s] = log_sigmoid_f(sf + bf[w]);
    }
}

// ---------------------------------------------------------------------------
// Kernel 2: per-head prefix sum (b) and prefix max (M). One block per head.
// Hillis-Steele, double buffered, 2048 elements / 1024 threads.
// ---------------------------------------------------------------------------
__global__ __launch_bounds__(1024) void scan_kernel()
{
    __shared__ float sA[S], sB[S];
    int h = blockIdx.x, tid = threadIdx.x;
    for (int i = tid; i < S; i += 1024) sA[i] = g_logf[h * S + i];
    __syncthreads();
    float* in = sA; float* out = sB;
    for (int off = 1; off < S; off <<= 1) {
        for (int i = tid; i < S; i += 1024) {
            float vv = in[i];
            if (i >= off) vv += in[i - off];
            out[i] = vv;
        }
        __syncthreads();
        float* t = in; in = out; out = t;
    }
    // 'in' holds b (inclusive cumsum)
    for (int i = tid; i < S; i += 1024) {
        float b = in[i];
        g_b[h * S + i] = b;
        float a = g_ig[h * S + i] - b;
        g_a[h * S + i] = a;
        out[i] = a;
    }
    __syncthreads();
    { float* t = in; in = out; out = t; }   // 'in' now holds a
    for (int off = 1; off < S; off <<= 1) {
        for (int i = tid; i < S; i += 1024) {
            float vv = in[i];
            if (i >= off) vv = fmaxf(vv, in[i - off]);
            out[i] = vv;
        }
        __syncthreads();
        float* t = in; in = out; out = t;
    }
    for (int i = tid; i < S; i += 1024) g_M[h * S + i] = in[i];
}

// ---------------------------------------------------------------------------
// Kernel 3: fused causal weighted attention.
// h[s] = (1/(norm+eps)) * sum_{t<=s} (q_s.k_t)*scale * exp(a[t]-M[s]) * v_t
// norm = max(|rowsum|, exp(-b[s]-M[s]))
// Block: (head, s-tile of 64 rows). 256 threads: tx=tid&15, ty=tid>>4.
// Score tile 64x32: each thread 4 rows x 2 cols. PV: 4 rows x 8 dims.
// ---------------------------------------------------------------------------
__global__ __launch_bounds__(256, 2) void attn_kernel(
    const float* __restrict__ q, const float* __restrict__ k,
    const float* __restrict__ v)
{
    extern __shared__ float sm[];
    float* Qs = sm;                          // [DH][QS_STRIDE] transposed
    float* Ks = Qs + DH * QS_STRIDE;         // [DH][KS_STRIDE] transposed
    float* Vs = Ks + DH * KS_STRIDE;         // [BT][DH]
    float* Ps = Vs + BT * DH;                // [BS][PS_STRIDE]

    int h = blockIdx.y;
    int stile = (S / BS) - 1 - blockIdx.x;   // biggest tiles launch first
    int s0 = stile * BS;
    int tid = threadIdx.x;
    int tx = tid & 15, ty = tid >> 4;

    // Load Q tile transposed (coalesced gmem, strided smem store)
    for (int idx = tid; idx < BS * DH; idx += 256) {
        int r = idx >> 7;        // 0..63
        int kk = idx & 127;
        Qs[kk * QS_STRIDE + r] = q[(size_t)(s0 + r) * E + h * DH + kk];
    }

    float Mrow[4], brow[4];
#pragma unroll
    for (int i = 0; i < 4; i++) {
        int srow = s0 + 4 * ty + i;
        Mrow[i] = g_M[h * S + srow];
        brow[i] = g_b[h * S + srow];
    }

    float acc[4][8];
#pragma unroll
    for (int i = 0; i < 4; i++)
#pragma unroll
        for (int j = 0; j < 8; j++) acc[i][j] = 0.f;
    float dsum[4] = {0.f, 0.f, 0.f, 0.f};

    const float scale = 0.0883883476483184406f;  // 1/sqrt(128)
    int nT = s0 / BT + 2;

    for (int t = 0; t < nT; t++) {
        int t0 = t * BT;
        __syncthreads();   // previous PV done before overwriting K/V
        for (int idx = tid; idx < BT * DH; idx += 256) {
            int c = idx >> 7;       // 0..31
            int kk = idx & 127;
            float kv = k[(size_t)(t0 + c) * E + h * DH + kk];
            float vv = v[(size_t)(t0 + c) * E + h * DH + kk];
            Ks[kk * KS_STRIDE + c] = kv;
            Vs[c * DH + kk] = vv;
        }
        __syncthreads();

        // scores: 64x32 = (64xDH) x (DHx32)
        float sc[4][2];
#pragma unroll
        for (int i = 0; i < 4; i++) { sc[i][0] = 0.f; sc[i][1] = 0.f; }
#pragma unroll 8
        for (int kk = 0; kk < DH; kk++) {
            float2 kv = *(const float2*)&Ks[kk * KS_STRIDE + 2 * tx];
            float4 qv = *(const float4*)&Qs[kk * QS_STRIDE + 4 * ty];
            sc[0][0] += qv.x * kv.x; sc[0][1] += qv.x * kv.y;
            sc[1][0] += qv.y * kv.x; sc[1][1] += qv.y * kv.y;
            sc[2][0] += qv.z * kv.x; sc[2][1] += qv.z * kv.y;
            sc[3][0] += qv.w * kv.x; sc[3][1] += qv.w * kv.y;
        }

        // apply decay weights + causal mask; write P; accumulate row sums
        float a0 = g_a[h * S + t0 + 2 * tx];
        float a1 = g_a[h * S + t0 + 2 * tx + 1];
#pragma unroll
        for (int i = 0; i < 4; i++) {
            int srow = s0 + 4 * ty + i;
            int tc0 = t0 + 2 * tx;
            float w0 = (tc0     <= srow) ? expf(a0 - Mrow[i]) : 0.f;
            float w1 = (tc0 + 1 <= srow) ? expf(a1 - Mrow[i]) : 0.f;
            float p0 = sc[i][0] * scale * w0;
            float p1 = sc[i][1] * scale * w1;
            Ps[(4 * ty + i) * PS_STRIDE + 2 * tx]     = p0;
            Ps[(4 * ty + i) * PS_STRIDE + 2 * tx + 1] = p1;
            dsum[i] += p0 + p1;
        }
        __syncthreads();

        // PV: acc[64x128] += P[64x32] @ V[32x128]
#pragma unroll 4
        for (int tt = 0; tt < BT; tt++) {
            float4 v0 = *(const float4*)&Vs[tt * DH + 8 * tx];
            float4 v1 = *(const float4*)&Vs[tt * DH + 8 * tx + 4];
#pragma unroll
            for (int i = 0; i < 4; i++) {
                float p = Ps[(4 * ty + i) * PS_STRIDE + tt];
                acc[i][0] += p * v0.x; acc[i][1] += p * v0.y;
                acc[i][2] += p * v0.z; acc[i][3] += p * v0.w;
                acc[i][4] += p * v1.x; acc[i][5] += p * v1.y;
                acc[i][6] += p * v1.z; acc[i][7] += p * v1.w;
            }
        }
    }

    // reduce dsum across the 16 tx lanes (lanes 0-15 / 16-31 are separate ty)
#pragma unroll
    for (int i = 0; i < 4; i++) {
#pragma unroll
        for (int o = 8; o > 0; o >>= 1)
            dsum[i] += __shfl_xor_sync(0xffffffffu, dsum[i], o);
    }

#pragma unroll
    for (int i = 0; i < 4; i++) {
        int srow = s0 + 4 * ty + i;
        float norm = fmaxf(fabsf(dsum[i]), expf(-(brow[i] + Mrow[i])));
        float inv = 1.f / (norm + 1e-6f);
#pragma unroll
        for (int j = 0; j < 8; j++)
            g_h[(size_t)srow * E + h * DH + 8 * tx + j] = acc[i][j] * inv;
    }
}

// ---------------------------------------------------------------------------
// Kernel 4: residual layer norm: out = (h-mu)*rsqrt(var+1e-5) * (1+ln_weight)
// Two-pass for variance accuracy. One block per row.
// ---------------------------------------------------------------------------
__global__ __launch_bounds__(256) void ln_kernel(
    const float* __restrict__ lnw, float* __restrict__ out)
{
    int s = blockIdx.x;
    int tid = threadIdx.x;
    int lane = tid & 31, wid = tid >> 5;
    __shared__ float red[8];
    __shared__ float s_mu, s_inv;
    const float* hr = g_h + (size_t)s * E;

    float sum = 0.f;
    for (int e = tid; e < E; e += 256) sum += hr[e];
#pragma unroll
    for (int o = 16; o > 0; o >>= 1) sum += __shfl_xor_sync(0xffffffffu, sum, o);
    if (lane == 0) red[wid] = sum;
    __syncthreads();
    if (tid == 0) {
        float t = 0.f;
        for (int i = 0; i < 8; i++) t += red[i];
        s_mu = t * (1.f / E);
    }
    __syncthreads();
    float mu = s_mu;

    float sq = 0.f;
    for (int e = tid; e < E; e += 256) {
        float d = hr[e] - mu;
        sq += d * d;
    }
#pragma unroll
    for (int o = 16; o > 0; o >>= 1) sq += __shfl_xor_sync(0xffffffffu, sq, o);
    if (lane == 0) red[wid] = sq;
    __syncthreads();
    if (tid == 0) {
        float t = 0.f;
        for (int i = 0; i < 8; i++) t += red[i];
        s_inv = rsqrtf(t * (1.f / E) + 1e-5f);
    }
    __syncthreads();
    float inv = s_inv;

    for (int e = tid; e < E; e += 256)
        out[(size_t)s * E + e] = (hr[e] - mu) * inv * (1.f + lnw[e]);
}

// ---------------------------------------------------------------------------
extern "C" void kernel_launch(void* const* d_in, const int* in_sizes, int n_in,
                              void* d_out, int out_size)
{
    const float* q   = (const float*)d_in[0];
    const float* k   = (const float*)d_in[1];
    const float* v   = (const float*)d_in[2];
    const float* Wi  = (const float*)d_in[3];
    const float* bi  = (const float*)d_in[4];
    const float* Wf  = (const float*)d_in[5];
    const float* bf  = (const float*)d_in[6];
    const float* lnw = (const float*)d_in[7];
    float* out = (float*)d_out;

    gates_kernel<<<S, 256>>>(q, k, v, Wi, bi, Wf, bf);
    scan_kernel<<<NH, 1024>>>();

    int smem_bytes = (DH * QS_STRIDE + DH * KS_STRIDE + BT * DH + BS * PS_STRIDE) * 4;
    cudaFuncSetAttribute(attn_kernel,
                         cudaFuncAttributeMaxDynamicSharedMemorySize, smem_bytes);
    attn_kernel<<<dim3(S / BS, NH), 256, smem_bytes>>>(q, k, v);

    ln_kernel<<<S, 256>>>(lnw, out);
}

// round 2
// speedup vs baseline: 1.6041x; 1.6041x over previous
#include <cuda_runtime.h>
#include <math.h>

#define S 2048
#define E 1024
#define NH 8
#define DH 128
#define BS 64
#define BT 64
#define QS_STR 132       // Q row stride (conflict-free broadcast pairs)
#define PS_STR 68        // P row stride
#define GR 8             // gate rows per block

// Scratch (allocation-free rule: __device__ globals)
__device__ float g_ig[NH * S];
__device__ float g_logf[NH * S];
__device__ float g_b[NH * S];     // inclusive cumsum of log_sigmoid(fg)
__device__ float g_a[NH * S];     // a[t] = ig[t] - b[t]
__device__ float g_M[NH * S];     // prefix max of a
__device__ float g_h[(size_t)S * E];

__device__ __forceinline__ float log_sigmoid_f(float x) {
    if (x >= 0.f) return -log1pf(expf(-x));
    return x - log1pf(expf(x));
}

// ---------------------------------------------------------------------------
// Kernel 1: gate projections. Block handles GR rows; q|k|v rows staged in smem
// so Wi/Wf stream from L2 once per block instead of once per row.
// warp w -> head w. 256 threads.
// ---------------------------------------------------------------------------
__global__ __launch_bounds__(256) void gates_kernel(
    const float* __restrict__ q, const float* __restrict__ k,
    const float* __restrict__ v,
    const float* __restrict__ Wi, const float* __restrict__ bi,
    const float* __restrict__ Wf, const float* __restrict__ bf)
{
    extern __shared__ float gin[];   // [GR][3*E]
    int s0 = blockIdx.x * GR;
    int tid = threadIdx.x;

    // load q|k|v rows, float4 coalesced
    for (int idx = tid; idx < GR * (E / 4); idx += 256) {
        int r = idx >> 8;            // E/4 = 256
        int c4 = idx & 255;
        float4* row = (float4*)(gin + r * 3 * E);
        row[c4]       = ((const float4*)(q + (size_t)(s0 + r) * E))[c4];
        row[256 + c4] = ((const float4*)(k + (size_t)(s0 + r) * E))[c4];
        row[512 + c4] = ((const float4*)(v + (size_t)(s0 + r) * E))[c4];
    }
    __syncthreads();

    int w = tid >> 5, lane = tid & 31;
    const float4* wi4 = (const float4*)(Wi + (size_t)w * 3 * E);
    const float4* wf4 = (const float4*)(Wf + (size_t)w * 3 * E);
    float bih = bi[w], bfh = bf[w];

    for (int r = 0; r < GR; r++) {
        const float4* g4 = (const float4*)(gin + r * 3 * E);
        float si = 0.f, sf = 0.f;
        for (int j = lane; j < 3 * E / 4; j += 32) {
            float4 g = g4[j];
            float4 a = wi4[j];
            float4 b = wf4[j];
            si += g.x * a.x + g.y * a.y + g.z * a.z + g.w * a.w;
            sf += g.x * b.x + g.y * b.y + g.z * b.z + g.w * b.w;
        }
#pragma unroll
        for (int o = 16; o > 0; o >>= 1) {
            si += __shfl_xor_sync(0xffffffffu, si, o);
            sf += __shfl_xor_sync(0xffffffffu, sf, o);
        }
        if (lane == 0) {
            g_ig[w * S + s0 + r] = si + bih;
            g_logf[w * S + s0 + r] = log_sigmoid_f(sf + bfh);
        }
    }
}

// ---------------------------------------------------------------------------
// Kernel 2: per-head prefix sum (b) and prefix max (M) via shfl two-level scan.
// Block = 1024 threads, each owns 2 consecutive elements. Grid = NH.
// ---------------------------------------------------------------------------
__global__ __launch_bounds__(1024) void scan_kernel()
{
    __shared__ float wsum[32], wmax[32];
    int h = blockIdx.x, tid = threadIdx.x;
    int lane = tid & 31, wid = tid >> 5;
    const float NEGINF = -3.4e38f;

    float x0 = g_logf[h * S + 2 * tid];
    float x1 = g_logf[h * S + 2 * tid + 1];
    float ts = x0 + x1;

    // warp-inclusive sum scan
    float sc = ts;
#pragma unroll
    for (int o = 1; o < 32; o <<= 1) {
        float n = __shfl_up_sync(0xffffffffu, sc, o);
        if (lane >= o) sc += n;
    }
    if (lane == 31) wsum[wid] = sc;
    __syncthreads();
    if (wid == 0) {
        float vv = wsum[lane];
#pragma unroll
        for (int o = 1; o < 32; o <<= 1) {
            float n = __shfl_up_sync(0xffffffffu, vv, o);
            if (lane >= o) vv += n;
        }
        wsum[lane] = vv;
    }
    __syncthreads();
    float off = (wid > 0) ? wsum[wid - 1] : 0.f;
    float b1 = off + sc;
    float b0 = b1 - x1;
    g_b[h * S + 2 * tid] = b0;
    g_b[h * S + 2 * tid + 1] = b1;

    float a0 = g_ig[h * S + 2 * tid] - b0;
    float a1 = g_ig[h * S + 2 * tid + 1] - b1;
    g_a[h * S + 2 * tid] = a0;
    g_a[h * S + 2 * tid + 1] = a1;

    // warp-inclusive max scan of per-thread max
    float tm = fmaxf(a0, a1);
    float mc = tm;
#pragma unroll
    for (int o = 1; o < 32; o <<= 1) {
        float n = __shfl_up_sync(0xffffffffu, mc, o);
        if (lane >= o) mc = fmaxf(mc, n);
    }
    if (lane == 31) wmax[wid] = mc;
    __syncthreads();
    if (wid == 0) {
        float vv = wmax[lane];
#pragma unroll
        for (int o = 1; o < 32; o <<= 1) {
            float n = __shfl_up_sync(0xffffffffu, vv, o);
            if (lane >= o) vv = fmaxf(vv, n);
        }
        wmax[lane] = vv;
    }
    __syncthreads();
    float moff = (wid > 0) ? wmax[wid - 1] : NEGINF;
    float me = __shfl_up_sync(0xffffffffu, mc, 1);   // exclusive within warp
    if (lane == 0) me = NEGINF;
    float prev = fmaxf(moff, me);
    float M0 = fmaxf(prev, a0);
    float M1 = fmaxf(M0, a1);
    g_M[h * S + 2 * tid] = M0;
    g_M[h * S + 2 * tid + 1] = M1;
}

// ---------------------------------------------------------------------------
// Kernel 3: fused causal weighted attention, 64x64 tiles, 4x4 thread tiles.
// Q row-major (stride 132, scale folded in), K row-major XOR-swizzled,
// V row-major (cols {4tx, 64+4tx}), P row-major stride 68.
// 256 threads: tx = tid&15 (cols), ty = tid>>4 (row groups of 4).
// ---------------------------------------------------------------------------
__global__ __launch_bounds__(256, 1) void attn_kernel(
    const float* __restrict__ q, const float* __restrict__ k,
    const float* __restrict__ v)
{
    extern __shared__ float sm[];
    float* Qs = sm;                        // [BS][QS_STR]
    float* Ks = Qs + BS * QS_STR;          // [BT][128] swizzled
    float* Vs = Ks + BT * 128;             // [BT][128]
    float* Ps = Vs + BT * 128;             // [BS][PS_STR]

    int h = blockIdx.y;
    int stile = (S / BS) - 1 - blockIdx.x;   // biggest first
    int s0 = stile * BS;
    int tid = threadIdx.x;
    int tx = tid & 15, ty = tid >> 4;
    const float scale = 0.0883883476483184406f;  // 1/sqrt(128)

    // Q tile: row-major, scale folded
    for (int idx = tid; idx < BS * DH; idx += 256) {
        int r = idx >> 7, kk = idx & 127;
        Qs[r * QS_STR + kk] = q[(size_t)(s0 + r) * E + h * DH + kk] * scale;
    }

    float Mrow[4], brow[4];
#pragma unroll
    for (int i = 0; i < 4; i++) {
        int srow = s0 + 4 * ty + i;
        Mrow[i] = g_M[h * S + srow];
        brow[i] = g_b[h * S + srow];
    }

    float acc[4][8];
#pragma unroll
    for (int i = 0; i < 4; i++)
#pragma unroll
        for (int j = 0; j < 8; j++) acc[i][j] = 0.f;
    float dsum[4] = {0.f, 0.f, 0.f, 0.f};

    const float* kbase = Ks + (4 * tx) * 128;
    const float* qbase = Qs + (4 * ty) * QS_STR;
    int txk = tx & 7;

    for (int t = 0; t <= stile; t++) {
        int t0 = t * BT;
        __syncthreads();   // prev PV done; safe to overwrite K/V
        // K: float4 slots with XOR swizzle p = s ^ ((c>>2)&7)
        for (int idx = tid; idx < BT * 32; idx += 256) {
            int c = idx >> 5, s = idx & 31;
            int p = s ^ ((c >> 2) & 7);
            float4 kv = ((const float4*)(k + (size_t)(t0 + c) * E + h * DH))[s];
            float4 vv = ((const float4*)(v + (size_t)(t0 + c) * E + h * DH))[s];
            *(float4*)&Ks[c * 128 + 4 * p] = kv;
            *(float4*)&Vs[c * 128 + 4 * s] = vv;
        }
        __syncthreads();

        // scores 64x64: per-thread 4x4 block, chunks of 4 kk
        float scr[4][4];
#pragma unroll
        for (int i = 0; i < 4; i++)
#pragma unroll
            for (int j = 0; j < 4; j++) scr[i][j] = 0.f;

#pragma unroll 4
        for (int ck = 0; ck < 32; ck++) {
            int swz = 4 * (ck ^ txk);
            float4 kf[4], qf[4];
#pragma unroll
            for (int j = 0; j < 4; j++)
                kf[j] = *(const float4*)(kbase + j * 128 + swz);
#pragma unroll
            for (int i = 0; i < 4; i++)
                qf[i] = *(const float4*)(qbase + i * QS_STR + 4 * ck);
#pragma unroll
            for (int i = 0; i < 4; i++)
#pragma unroll
                for (int j = 0; j < 4; j++)
                    scr[i][j] += qf[i].x * kf[j].x + qf[i].y * kf[j].y +
                                 qf[i].z * kf[j].z + qf[i].w * kf[j].w;
        }

        // apply decay weights (+ causal mask only on diagonal tile)
        float4 av = *(const float4*)&g_a[h * S + t0 + 4 * tx];
        bool diag = (t == stile);
#pragma unroll
        for (int i = 0; i < 4; i++) {
            float w0 = __expf(av.x - Mrow[i]);
            float w1 = __expf(av.y - Mrow[i]);
            float w2 = __expf(av.z - Mrow[i]);
            float w3 = __expf(av.w - Mrow[i]);
            if (diag) {
                int rr = 4 * ty + i;
                if (4 * tx     > rr) w0 = 0.f;
                if (4 * tx + 1 > rr) w1 = 0.f;
                if (4 * tx + 2 > rr) w2 = 0.f;
                if (4 * tx + 3 > rr) w3 = 0.f;
            }
            float p0 = scr[i][0] * w0;
            float p1 = scr[i][1] * w1;
            float p2 = scr[i][2] * w2;
            float p3 = scr[i][3] * w3;
            dsum[i] += (p0 + p1) + (p2 + p3);
            float4 pv = make_float4(p0, p1, p2, p3);
            *(float4*)&Ps[(4 * ty + i) * PS_STR + 4 * tx] = pv;
        }
        __syncthreads();

        // PV: acc[64x128] += P[64x64] @ V[64x128]
#pragma unroll 4
        for (int tt = 0; tt < BT; tt++) {
            float4 v0 = *(const float4*)&Vs[tt * 128 + 4 * tx];
            float4 v1 = *(const float4*)&Vs[tt * 128 + 64 + 4 * tx];
#pragma unroll
            for (int i = 0; i < 4; i++) {
                float p = Ps[(4 * ty + i) * PS_STR + tt];
                acc[i][0] += p * v0.x; acc[i][1] += p * v0.y;
                acc[i][2] += p * v0.z; acc[i][3] += p * v0.w;
                acc[i][4] += p * v1.x; acc[i][5] += p * v1.y;
                acc[i][6] += p * v1.z; acc[i][7] += p * v1.w;
            }
        }
    }

    // reduce dsum across the 16 tx lanes
#pragma unroll
    for (int i = 0; i < 4; i++) {
#pragma unroll
        for (int o = 8; o > 0; o >>= 1)
            dsum[i] += __shfl_xor_sync(0xffffffffu, dsum[i], o);
    }

#pragma unroll
    for (int i = 0; i < 4; i++) {
        int srow = s0 + 4 * ty + i;
        float norm = fmaxf(fabsf(dsum[i]), __expf(-(brow[i] + Mrow[i])));
        float inv = 1.f / (norm + 1e-6f);
        float4 o0 = make_float4(acc[i][0] * inv, acc[i][1] * inv,
                                acc[i][2] * inv, acc[i][3] * inv);
        float4 o1 = make_float4(acc[i][4] * inv, acc[i][5] * inv,
                                acc[i][6] * inv, acc[i][7] * inv);
        *(float4*)&g_h[(size_t)srow * E + h * DH + 4 * tx] = o0;
        *(float4*)&g_h[(size_t)srow * E + h * DH + 64 + 4 * tx] = o1;
    }
}

// ---------------------------------------------------------------------------
// Kernel 4: residual layer norm, single pass (sum + sumsq), float4.
// One block per row, 256 threads -> exactly one float4 per thread.
// ---------------------------------------------------------------------------
__global__ __launch_bounds__(256) void ln_kernel(
    const float* __restrict__ lnw, float* __restrict__ out)
{
    int s = blockIdx.x;
    int tid = threadIdx.x;
    int lane = tid & 31, wid = tid >> 5;
    __shared__ float rsum[8], rsq[8];
    __shared__ float s_mu, s_inv;

    float4 hv = ((const float4*)(g_h + (size_t)s * E))[tid];
    float sum = hv.x + hv.y + hv.z + hv.w;
    float sq = hv.x * hv.x + hv.y * hv.y + hv.z * hv.z + hv.w * hv.w;
#pragma unroll
    for (int o = 16; o > 0; o >>= 1) {
        sum += __shfl_xor_sync(0xffffffffu, sum, o);
        sq  += __shfl_xor_sync(0xffffffffu, sq, o);
    }
    if (lane == 0) { rsum[wid] = sum; rsq[wid] = sq; }
    __syncthreads();
    if (tid == 0) {
        float ts = 0.f, tq = 0.f;
        for (int i = 0; i < 8; i++) { ts += rsum[i]; tq += rsq[i]; }
        float mu = ts * (1.f / E);
        float var = tq * (1.f / E) - mu * mu;
        s_mu = mu;
        s_inv = rsqrtf(var + 1e-5f);
    }
    __syncthreads();
    float mu = s_mu, inv = s_inv;

    float4 wv = ((const float4*)lnw)[tid];
    float4 ov;
    ov.x = (hv.x - mu) * inv * (1.f + wv.x);
    ov.y = (hv.y - mu) * inv * (1.f + wv.y);
    ov.z = (hv.z - mu) * inv * (1.f + wv.z);
    ov.w = (hv.w - mu) * inv * (1.f + wv.w);
    ((float4*)(out + (size_t)s * E))[tid] = ov;
}

// ---------------------------------------------------------------------------
extern "C" void kernel_launch(void* const* d_in, const int* in_sizes, int n_in,
                              void* d_out, int out_size)
{
    const float* q   = (const float*)d_in[0];
    const float* k   = (const float*)d_in[1];
    const float* v   = (const float*)d_in[2];
    const float* Wi  = (const float*)d_in[3];
    const float* bi  = (const float*)d_in[4];
    const float* Wf  = (const float*)d_in[5];
    const float* bf  = (const float*)d_in[6];
    const float* lnw = (const float*)d_in[7];
    float* out = (float*)d_out;

    int gates_smem = GR * 3 * E * 4;
    cudaFuncSetAttribute(gates_kernel,
                         cudaFuncAttributeMaxDynamicSharedMemorySize, gates_smem);
    gates_kernel<<<S / GR, 256, gates_smem>>>(q, k, v, Wi, bi, Wf, bf);

    scan_kernel<<<NH, 1024>>>();

    int attn_smem = (BS * QS_STR + BT * 128 + BT * 128 + BS * PS_STR) * 4;
    cudaFuncSetAttribute(attn_kernel,
                         cudaFuncAttributeMaxDynamicSharedMemorySize, attn_smem);
    attn_kernel<<<dim3(S / BS, NH), 256, attn_smem>>>(q, k, v);

    ln_kernel<<<S, 256>>>(lnw, out);
}

// round 4
// speedup vs baseline: 2.9246x; 1.8232x over previous
#include <cuda_runtime.h>
#include <math.h>

#define S 2048
#define E 1024
#define NH 8
#define DH 128
#define BS 64        // q rows per attn block
#define BT 64        // keys per kv tile
#define QSTR 132     // ≡4 mod 32: frag reads conflict-free
#define KSTR 132
#define PSTR 132
#define VSTR 136     // ≡8 mod 32: PV B-frag reads conflict-free
#define GR 8         // gate rows per block

// Scratch (allocation-free rule: __device__ globals)
__device__ float g_ig[NH * S];
__device__ float g_logf[NH * S];
__device__ float g_b[NH * S];
__device__ float g_a[NH * S];
__device__ float g_M[NH * S];
__device__ float g_h[(size_t)S * E];

__device__ __forceinline__ float log_sigmoid_f(float x) {
    if (x >= 0.f) return -log1pf(expf(-x));
    return x - log1pf(expf(x));
}

__device__ __forceinline__ unsigned f2tf(float x) {
    unsigned u;
    asm("cvt.rna.tf32.f32 %0, %1;" : "=r"(u) : "f"(x));
    return u;
}

// split x into tf32 hi + tf32 lo (x ≈ hi + lo, lo error ~2^-24 of x)
__device__ __forceinline__ void split_tf(float x, unsigned& hi, unsigned& lo) {
    hi = f2tf(x);
    lo = f2tf(x - __uint_as_float(hi));
}

__device__ __forceinline__ void mma8(float* d, const unsigned* a, const unsigned* b) {
    asm volatile(
        "mma.sync.aligned.m16n8k8.row.col.f32.tf32.tf32.f32 "
        "{%0,%1,%2,%3},{%4,%5,%6,%7},{%8,%9},{%0,%1,%2,%3};"
        : "+f"(d[0]), "+f"(d[1]), "+f"(d[2]), "+f"(d[3])
        : "r"(a[0]), "r"(a[1]), "r"(a[2]), "r"(a[3]), "r"(b[0]), "r"(b[1]));
}

// ---------------------------------------------------------------------------
// Kernel 1: gate projections (unchanged)
// ---------------------------------------------------------------------------
__global__ __launch_bounds__(256) void gates_kernel(
    const float* __restrict__ q, const float* __restrict__ k,
    const float* __restrict__ v,
    const float* __restrict__ Wi, const float* __restrict__ bi,
    const float* __restrict__ Wf, const float* __restrict__ bf)
{
    extern __shared__ float gin[];   // [GR][3*E]
    int s0 = blockIdx.x * GR;
    int tid = threadIdx.x;

    for (int idx = tid; idx < GR * (E / 4); idx += 256) {
        int r = idx >> 8;
        int c4 = idx & 255;
        float4* row = (float4*)(gin + r * 3 * E);
        row[c4]       = ((const float4*)(q + (size_t)(s0 + r) * E))[c4];
        row[256 + c4] = ((const float4*)(k + (size_t)(s0 + r) * E))[c4];
        row[512 + c4] = ((const float4*)(v + (size_t)(s0 + r) * E))[c4];
    }
    __syncthreads();

    int w = tid >> 5, lane = tid & 31;
    const float4* wi4 = (const float4*)(Wi + (size_t)w * 3 * E);
    const float4* wf4 = (const float4*)(Wf + (size_t)w * 3 * E);
    float bih = bi[w], bfh = bf[w];

    for (int r = 0; r < GR; r++) {
        const float4* g4 = (const float4*)(gin + r * 3 * E);
        float si = 0.f, sf = 0.f;
        for (int j = lane; j < 3 * E / 4; j += 32) {
            float4 g = g4[j];
            float4 a = wi4[j];
            float4 b = wf4[j];
            si += g.x * a.x + g.y * a.y + g.z * a.z + g.w * a.w;
            sf += g.x * b.x + g.y * b.y + g.z * b.z + g.w * b.w;
        }
#pragma unroll
        for (int o = 16; o > 0; o >>= 1) {
            si += __shfl_xor_sync(0xffffffffu, si, o);
            sf += __shfl_xor_sync(0xffffffffu, sf, o);
        }
        if (lane == 0) {
            g_ig[w * S + s0 + r] = si + bih;
            g_logf[w * S + s0 + r] = log_sigmoid_f(sf + bfh);
        }
    }
}

// ---------------------------------------------------------------------------
// Kernel 2: per-head prefix sum (b) and prefix max (M) (unchanged)
// ---------------------------------------------------------------------------
__global__ __launch_bounds__(1024) void scan_kernel()
{
    __shared__ float wsum[32], wmax[32];
    int h = blockIdx.x, tid = threadIdx.x;
    int lane = tid & 31, wid = tid >> 5;
    const float NEGINF = -3.4e38f;

    float x0 = g_logf[h * S + 2 * tid];
    float x1 = g_logf[h * S + 2 * tid + 1];
    float ts = x0 + x1;

    float sc = ts;
#pragma unroll
    for (int o = 1; o < 32; o <<= 1) {
        float n = __shfl_up_sync(0xffffffffu, sc, o);
        if (lane >= o) sc += n;
    }
    if (lane == 31) wsum[wid] = sc;
    __syncthreads();
    if (wid == 0) {
        float vv = wsum[lane];
#pragma unroll
        for (int o = 1; o < 32; o <<= 1) {
            float n = __shfl_up_sync(0xffffffffu, vv, o);
            if (lane >= o) vv += n;
        }
        wsum[lane] = vv;
    }
    __syncthreads();
    float off = (wid > 0) ? wsum[wid - 1] : 0.f;
    float b1 = off + sc;
    float b0 = b1 - x1;
    g_b[h * S + 2 * tid] = b0;
    g_b[h * S + 2 * tid + 1] = b1;

    float a0 = g_ig[h * S + 2 * tid] - b0;
    float a1 = g_ig[h * S + 2 * tid + 1] - b1;
    g_a[h * S + 2 * tid] = a0;
    g_a[h * S + 2 * tid + 1] = a1;

    float tm = fmaxf(a0, a1);
    float mc = tm;
#pragma unroll
    for (int o = 1; o < 32; o <<= 1) {
        float n = __shfl_up_sync(0xffffffffu, mc, o);
        if (lane >= o) mc = fmaxf(mc, n);
    }
    if (lane == 31) wmax[wid] = mc;
    __syncthreads();
    if (wid == 0) {
        float vv = wmax[lane];
#pragma unroll
        for (int o = 1; o < 32; o <<= 1) {
            float n = __shfl_up_sync(0xffffffffu, vv, o);
            if (lane >= o) vv = fmaxf(vv, n);
        }
        wmax[lane] = vv;
    }
    __syncthreads();
    float moff = (wid > 0) ? wmax[wid - 1] : NEGINF;
    float me = __shfl_up_sync(0xffffffffu, mc, 1);
    if (lane == 0) me = NEGINF;
    float prev = fmaxf(moff, me);
    float M0 = fmaxf(prev, a0);
    float M1 = fmaxf(M0, a1);
    g_M[h * S + 2 * tid] = M0;
    g_M[h * S + 2 * tid + 1] = M1;
}

// ---------------------------------------------------------------------------
// Kernel 3: 3xTF32 tensor-core causal weighted attention.
// All operands split hi/lo; each logical MMA = hihi + hilo + lohi.
// Block = 64 q-rows x 1 head, 8 warps. KV tiles of 64 keys.
// QK warp tile 32x16 (wy 2 x wx 4); PV warp tile 32x32.
// Phi/Plo alias Khi/Klo.
// ---------------------------------------------------------------------------
__global__ __launch_bounds__(256, 1) void attn_kernel(
    const float* __restrict__ q, const float* __restrict__ k,
    const float* __restrict__ v)
{
    extern __shared__ unsigned smu[];
    unsigned* Qhi = smu;                   // [64][QSTR]
    unsigned* Qlo = Qhi + BS * QSTR;
    unsigned* Khi = Qlo + BS * QSTR;       // [64][KSTR] (aliased by Phi)
    unsigned* Klo = Khi + BT * KSTR;       // (aliased by Plo)
    unsigned* Vhi = Klo + BT * KSTR;       // [64][VSTR]
    unsigned* Vlo = Vhi + BT * VSTR;
    float* dss = (float*)(Vlo + BT * VSTR); // [64][4]
    unsigned* Phi = Khi;
    unsigned* Plo = Klo;

    int blk = blockIdx.x;
    int st = (S / BS - 1) - (blk >> 3);    // biggest s-tiles first
    int h = blk & 7;
    int s0 = st * BS;
    int tid = threadIdx.x;
    int wid = tid >> 5, lane = tid & 31;
    int g = lane >> 2, tq = lane & 3;
    int wy = wid >> 2, wx = wid & 3;
    const float scale = 0.0883883476483184406f;  // 1/sqrt(128)

    // stage Q (scaled, split)
    for (int idx = tid; idx < BS * 32; idx += 256) {
        int r = idx >> 5, c4 = idx & 31;
        float4 qv = *(const float4*)(q + (size_t)(s0 + r) * E + h * DH + 4 * c4);
        uint4 uh, ul;
        split_tf(qv.x * scale, uh.x, ul.x);
        split_tf(qv.y * scale, uh.y, ul.y);
        split_tf(qv.z * scale, uh.z, ul.z);
        split_tf(qv.w * scale, uh.w, ul.w);
        *(uint4*)&Qhi[r * QSTR + 4 * c4] = uh;
        *(uint4*)&Qlo[r * QSTR + 4 * c4] = ul;
    }

    float Mr[2][2], br[2][2];
#pragma unroll
    for (int mt = 0; mt < 2; mt++)
#pragma unroll
        for (int hf = 0; hf < 2; hf++) {
            int r = s0 + wy * 32 + mt * 16 + hf * 8 + g;
            Mr[mt][hf] = g_M[h * S + r];
            br[mt][hf] = g_b[h * S + r];
        }

    float acc[2][4][4];
#pragma unroll
    for (int mt = 0; mt < 2; mt++)
#pragma unroll
        for (int nt = 0; nt < 4; nt++)
#pragma unroll
            for (int i = 0; i < 4; i++) acc[mt][nt][i] = 0.f;
    float ds[2][2] = {0.f, 0.f, 0.f, 0.f};

    int nT = st + 1;

    for (int t = 0; t < nT; t++) {
        int t0 = t * BT;
        __syncthreads();   // prev PV reads done; Q staged (t=0)
        // stage K,V (split)
        for (int idx = tid; idx < BT * 32; idx += 256) {
            int r = idx >> 5, c4 = idx & 31;
            float4 kv = *(const float4*)(k + (size_t)(t0 + r) * E + h * DH + 4 * c4);
            float4 vv = *(const float4*)(v + (size_t)(t0 + r) * E + h * DH + 4 * c4);
            uint4 kh, kl, vh, vl;
            split_tf(kv.x, kh.x, kl.x); split_tf(kv.y, kh.y, kl.y);
            split_tf(kv.z, kh.z, kl.z); split_tf(kv.w, kh.w, kl.w);
            split_tf(vv.x, vh.x, vl.x); split_tf(vv.y, vh.y, vl.y);
            split_tf(vv.z, vh.z, vl.z); split_tf(vv.w, vh.w, vl.w);
            *(uint4*)&Khi[r * KSTR + 4 * c4] = kh;
            *(uint4*)&Klo[r * KSTR + 4 * c4] = kl;
            *(uint4*)&Vhi[r * VSTR + 4 * c4] = vh;
            *(uint4*)&Vlo[r * VSTR + 4 * c4] = vl;
        }
        __syncthreads();

        // ---- QK^T: scores 64x64, warp tile 32x16, 3xtf32 ----
        float sc[2][2][4];
#pragma unroll
        for (int mt = 0; mt < 2; mt++)
#pragma unroll
            for (int nt = 0; nt < 2; nt++)
#pragma unroll
                for (int i = 0; i < 4; i++) sc[mt][nt][i] = 0.f;

#pragma unroll
        for (int c = 0; c < 16; c++) {
            unsigned ah[2][4], al[2][4], bh[2][2], bl[2][2];
#pragma unroll
            for (int mt = 0; mt < 2; mt++) {
                int r0 = wy * 32 + mt * 16 + g;
                int co = c * 8 + tq;
                ah[mt][0] = Qhi[r0 * QSTR + co];
                ah[mt][1] = Qhi[(r0 + 8) * QSTR + co];
                ah[mt][2] = Qhi[r0 * QSTR + co + 4];
                ah[mt][3] = Qhi[(r0 + 8) * QSTR + co + 4];
                al[mt][0] = Qlo[r0 * QSTR + co];
                al[mt][1] = Qlo[(r0 + 8) * QSTR + co];
                al[mt][2] = Qlo[r0 * QSTR + co + 4];
                al[mt][3] = Qlo[(r0 + 8) * QSTR + co + 4];
            }
#pragma unroll
            for (int nt = 0; nt < 2; nt++) {
                int key = wx * 16 + nt * 8 + g;
                int co = c * 8 + tq;
                bh[nt][0] = Khi[key * KSTR + co];
                bh[nt][1] = Khi[key * KSTR + co + 4];
                bl[nt][0] = Klo[key * KSTR + co];
                bl[nt][1] = Klo[key * KSTR + co + 4];
            }
#pragma unroll
            for (int mt = 0; mt < 2; mt++)
#pragma unroll
                for (int nt = 0; nt < 2; nt++) {
                    mma8(sc[mt][nt], ah[mt], bh[nt]);
                    mma8(sc[mt][nt], ah[mt], bl[nt]);
                    mma8(sc[mt][nt], al[mt], bh[nt]);
                }
        }
        __syncthreads();   // QK reads of K done before P overwrites

        // ---- decay weights + causal mask; P (split) -> smem; dsum ----
        bool lastT = (t == nT - 1);
#pragma unroll
        for (int nt = 0; nt < 2; nt++) {
            int colL = wx * 16 + nt * 8 + 2 * tq;
            int col0 = t0 + colL;
            float2 a2 = *(const float2*)&g_a[h * S + col0];
#pragma unroll
            for (int mt = 0; mt < 2; mt++) {
                int r0l = wy * 32 + mt * 16 + g;
                float w0 = __expf(a2.x - Mr[mt][0]);
                float w1 = __expf(a2.y - Mr[mt][0]);
                float w2 = __expf(a2.x - Mr[mt][1]);
                float w3 = __expf(a2.y - Mr[mt][1]);
                if (lastT) {
                    int gr0 = s0 + r0l, gr1 = gr0 + 8;
                    if (col0     > gr0) w0 = 0.f;
                    if (col0 + 1 > gr0) w1 = 0.f;
                    if (col0     > gr1) w2 = 0.f;
                    if (col0 + 1 > gr1) w3 = 0.f;
                }
                float p0 = sc[mt][nt][0] * w0, p1 = sc[mt][nt][1] * w1;
                float p2 = sc[mt][nt][2] * w2, p3 = sc[mt][nt][3] * w3;
                ds[mt][0] += p0 + p1;
                ds[mt][1] += p2 + p3;
                uint2 uh0, ul0, uh1, ul1;
                split_tf(p0, uh0.x, ul0.x); split_tf(p1, uh0.y, ul0.y);
                split_tf(p2, uh1.x, ul1.x); split_tf(p3, uh1.y, ul1.y);
                *(uint2*)&Phi[r0l * PSTR + colL] = uh0;
                *(uint2*)&Plo[r0l * PSTR + colL] = ul0;
                *(uint2*)&Phi[(r0l + 8) * PSTR + colL] = uh1;
                *(uint2*)&Plo[(r0l + 8) * PSTR + colL] = ul1;
            }
        }
        __syncthreads();

        // ---- PV: acc[64x128] += P[64x64] @ V[64x128], 3xtf32 ----
#pragma unroll
        for (int c = 0; c < 8; c++) {
            unsigned ah[2][4], al[2][4], bh[4][2], bl[4][2];
#pragma unroll
            for (int mt = 0; mt < 2; mt++) {
                int r0 = wy * 32 + mt * 16 + g;
                int co = c * 8 + tq;
                ah[mt][0] = Phi[r0 * PSTR + co];
                ah[mt][1] = Phi[(r0 + 8) * PSTR + co];
                ah[mt][2] = Phi[r0 * PSTR + co + 4];
                ah[mt][3] = Phi[(r0 + 8) * PSTR + co + 4];
                al[mt][0] = Plo[r0 * PSTR + co];
                al[mt][1] = Plo[(r0 + 8) * PSTR + co];
                al[mt][2] = Plo[r0 * PSTR + co + 4];
                al[mt][3] = Plo[(r0 + 8) * PSTR + co + 4];
            }
#pragma unroll
            for (int nt = 0; nt < 4; nt++) {
                int dh = wx * 32 + nt * 8 + g;
                int vr = c * 8 + tq;
                bh[nt][0] = Vhi[vr * VSTR + dh];
                bh[nt][1] = Vhi[(vr + 4) * VSTR + dh];
                bl[nt][0] = Vlo[vr * VSTR + dh];
                bl[nt][1] = Vlo[(vr + 4) * VSTR + dh];
            }
#pragma unroll
            for (int mt = 0; mt < 2; mt++)
#pragma unroll
                for (int nt = 0; nt < 4; nt++) {
                    mma8(acc[mt][nt], ah[mt], bh[nt]);
                    mma8(acc[mt][nt], ah[mt], bl[nt]);
                    mma8(acc[mt][nt], al[mt], bh[nt]);
                }
        }
    }

    // ---- dsum: quad shfl, then cross-warp (wx) via smem ----
#pragma unroll
    for (int mt = 0; mt < 2; mt++)
#pragma unroll
        for (int hf = 0; hf < 2; hf++) {
            float vds = ds[mt][hf];
            vds += __shfl_xor_sync(0xffffffffu, vds, 1);
            vds += __shfl_xor_sync(0xffffffffu, vds, 2);
            if (tq == 0)
                dss[(wy * 32 + mt * 16 + hf * 8 + g) * 4 + wx] = vds;
        }
    __syncthreads();

    // ---- normalize + store ----
#pragma unroll
    for (int mt = 0; mt < 2; mt++) {
        float inv[2];
#pragma unroll
        for (int hf = 0; hf < 2; hf++) {
            int rl = wy * 32 + mt * 16 + hf * 8 + g;
            float tot = dss[rl * 4 + 0] + dss[rl * 4 + 1] +
                        dss[rl * 4 + 2] + dss[rl * 4 + 3];
            float nrm = fmaxf(fabsf(tot), __expf(-(br[mt][hf] + Mr[mt][hf])));
            inv[hf] = 1.f / (nrm + 1e-6f);
        }
#pragma unroll
        for (int nt = 0; nt < 4; nt++) {
            int dh = wx * 32 + nt * 8 + 2 * tq;
            int r0 = s0 + wy * 32 + mt * 16 + g;
            float2 o0 = make_float2(acc[mt][nt][0] * inv[0], acc[mt][nt][1] * inv[0]);
            float2 o1 = make_float2(acc[mt][nt][2] * inv[1], acc[mt][nt][3] * inv[1]);
            *(float2*)&g_h[(size_t)r0 * E + h * DH + dh] = o0;
            *(float2*)&g_h[(size_t)(r0 + 8) * E + h * DH + dh] = o1;
        }
    }
}

// ---------------------------------------------------------------------------
// Kernel 4: residual layer norm (unchanged)
// ---------------------------------------------------------------------------
__global__ __launch_bounds__(256) void ln_kernel(
    const float* __restrict__ lnw, float* __restrict__ out)
{
    int s = blockIdx.x;
    int tid = threadIdx.x;
    int lane = tid & 31, wid = tid >> 5;
    __shared__ float rsum[8], rsq[8];
    __shared__ float s_mu, s_inv;

    float4 hv = ((const float4*)(g_h + (size_t)s * E))[tid];
    float sum = hv.x + hv.y + hv.z + hv.w;
    float sq = hv.x * hv.x + hv.y * hv.y + hv.z * hv.z + hv.w * hv.w;
#pragma unroll
    for (int o = 16; o > 0; o >>= 1) {
        sum += __shfl_xor_sync(0xffffffffu, sum, o);
        sq  += __shfl_xor_sync(0xffffffffu, sq, o);
    }
    if (lane == 0) { rsum[wid] = sum; rsq[wid] = sq; }
    __syncthreads();
    if (tid == 0) {
        float ts = 0.f, tqv = 0.f;
        for (int i = 0; i < 8; i++) { ts += rsum[i]; tqv += rsq[i]; }
        float mu = ts * (1.f / E);
        float var = tqv * (1.f / E) - mu * mu;
        s_mu = mu;
        s_inv = rsqrtf(var + 1e-5f);
    }
    __syncthreads();
    float mu = s_mu, inv = s_inv;

    float4 wv = ((const float4*)lnw)[tid];
    float4 ov;
    ov.x = (hv.x - mu) * inv * (1.f + wv.x);
    ov.y = (hv.y - mu) * inv * (1.f + wv.y);
    ov.z = (hv.z - mu) * inv * (1.f + wv.z);
    ov.w = (hv.w - mu) * inv * (1.f + wv.w);
    ((float4*)(out + (size_t)s * E))[tid] = ov;
}

// ---------------------------------------------------------------------------
extern "C" void kernel_launch(void* const* d_in, const int* in_sizes, int n_in,
                              void* d_out, int out_size)
{
    const float* q   = (const float*)d_in[0];
    const float* k   = (const float*)d_in[1];
    const float* v   = (const float*)d_in[2];
    const float* Wi  = (const float*)d_in[3];
    const float* bi  = (const float*)d_in[4];
    const float* Wf  = (const float*)d_in[5];
    const float* bf  = (const float*)d_in[6];
    const float* lnw = (const float*)d_in[7];
    float* out = (float*)d_out;

    int gates_smem = GR * 3 * E * 4;
    cudaFuncSetAttribute(gates_kernel,
                         cudaFuncAttributeMaxDynamicSharedMemorySize, gates_smem);
    gates_kernel<<<S / GR, 256, gates_smem>>>(q, k, v, Wi, bi, Wf, bf);

    scan_kernel<<<NH, 1024>>>();

    int attn_smem = (2 * BS * QSTR + 2 * BT * KSTR + 2 * BT * VSTR) * 4 + BS * 4 * 4;
    cudaFuncSetAttribute(attn_kernel,
                         cudaFuncAttributeMaxDynamicSharedMemorySize, attn_smem);
    attn_kernel<<<(S / BS) * NH, 256, attn_smem>>>(q, k, v);

    ln_kernel<<<S, 256>>>(lnw, out);
}

// round 5
// speedup vs baseline: 3.3038x; 1.1296x over previous
#include <cuda_runtime.h>
#include <cuda_bf16.h>
#include <math.h>

#define S 2048
#define E 1024
#define NH 8
#define DH 128
#define BS 64        // q rows per attn block
#define BT 64        // keys per kv tile
#define QSTR 68      // Q/K word stride (bf16x2 words), ≡4 mod 32
#define KSTR 68
#define PSTR 36      // P word stride, ≡4 mod 32
#define VSTR 136     // V pair-row word stride, ≡8 mod 32
#define GR 8         // gate rows per block

// Scratch (allocation-free rule: __device__ globals)
__device__ float g_ig[NH * S];
__device__ float g_logf[NH * S];
__device__ float g_b[NH * S];
__device__ float g_a[NH * S];
__device__ float g_M[NH * S];
__device__ float g_h[(size_t)S * E];

__device__ __forceinline__ float log_sigmoid_f(float x) {
    if (x >= 0.f) return -log1pf(expf(-x));
    return x - log1pf(expf(x));
}

__device__ __forceinline__ unsigned short bfbits(float x) {
    __nv_bfloat16 b = __float2bfloat16_rn(x);
    return *reinterpret_cast<unsigned short*>(&b);
}
__device__ __forceinline__ float bits2f(unsigned short u) {
    __nv_bfloat16 b = *reinterpret_cast<__nv_bfloat16*>(&u);
    return __bfloat162float(b);
}
// x ≈ hi + lo, residual ≤ 2^-16 |x|
__device__ __forceinline__ void split2(float x, unsigned short& h, unsigned short& l) {
    h = bfbits(x);
    l = bfbits(x - bits2f(h));
}
__device__ __forceinline__ unsigned pk(unsigned short e0, unsigned short e1) {
    return (unsigned)e0 | ((unsigned)e1 << 16);   // e0 = lower k index
}

__device__ __forceinline__ void mma16(float* d, const unsigned* a, const unsigned* b) {
    asm volatile(
        "mma.sync.aligned.m16n8k16.row.col.f32.bf16.bf16.f32 "
        "{%0,%1,%2,%3},{%4,%5,%6,%7},{%8,%9},{%0,%1,%2,%3};"
        : "+f"(d[0]), "+f"(d[1]), "+f"(d[2]), "+f"(d[3])
        : "r"(a[0]), "r"(a[1]), "r"(a[2]), "r"(a[3]), "r"(b[0]), "r"(b[1]));
}

// ---------------------------------------------------------------------------
// Kernel 1: gate projections (unchanged)
// ---------------------------------------------------------------------------
__global__ __launch_bounds__(256) void gates_kernel(
    const float* __restrict__ q, const float* __restrict__ k,
    const float* __restrict__ v,
    const float* __restrict__ Wi, const float* __restrict__ bi,
    const float* __restrict__ Wf, const float* __restrict__ bf)
{
    extern __shared__ float gin[];   // [GR][3*E]
    int s0 = blockIdx.x * GR;
    int tid = threadIdx.x;

    for (int idx = tid; idx < GR * (E / 4); idx += 256) {
        int r = idx >> 8;
        int c4 = idx & 255;
        float4* row = (float4*)(gin + r * 3 * E);
        row[c4]       = ((const float4*)(q + (size_t)(s0 + r) * E))[c4];
        row[256 + c4] = ((const float4*)(k + (size_t)(s0 + r) * E))[c4];
        row[512 + c4] = ((const float4*)(v + (size_t)(s0 + r) * E))[c4];
    }
    __syncthreads();

    int w = tid >> 5, lane = tid & 31;
    const float4* wi4 = (const float4*)(Wi + (size_t)w * 3 * E);
    const float4* wf4 = (const float4*)(Wf + (size_t)w * 3 * E);
    float bih = bi[w], bfh = bf[w];

    for (int r = 0; r < GR; r++) {
        const float4* g4 = (const float4*)(gin + r * 3 * E);
        float si = 0.f, sf = 0.f;
        for (int j = lane; j < 3 * E / 4; j += 32) {
            float4 g = g4[j];
            float4 a = wi4[j];
            float4 b = wf4[j];
            si += g.x * a.x + g.y * a.y + g.z * a.z + g.w * a.w;
            sf += g.x * b.x + g.y * b.y + g.z * b.z + g.w * b.w;
        }
#pragma unroll
        for (int o = 16; o > 0; o >>= 1) {
            si += __shfl_xor_sync(0xffffffffu, si, o);
            sf += __shfl_xor_sync(0xffffffffu, sf, o);
        }
        if (lane == 0) {
            g_ig[w * S + s0 + r] = si + bih;
            g_logf[w * S + s0 + r] = log_sigmoid_f(sf + bfh);
        }
    }
}

// ---------------------------------------------------------------------------
// Kernel 2: per-head prefix sum (b) and prefix max (M) (unchanged)
// ---------------------------------------------------------------------------
__global__ __launch_bounds__(1024) void scan_kernel()
{
    __shared__ float wsum[32], wmax[32];
    int h = blockIdx.x, tid = threadIdx.x;
    int lane = tid & 31, wid = tid >> 5;
    const float NEGINF = -3.4e38f;

    float x0 = g_logf[h * S + 2 * tid];
    float x1 = g_logf[h * S + 2 * tid + 1];
    float ts = x0 + x1;

    float sc = ts;
#pragma unroll
    for (int o = 1; o < 32; o <<= 1) {
        float n = __shfl_up_sync(0xffffffffu, sc, o);
        if (lane >= o) sc += n;
    }
    if (lane == 31) wsum[wid] = sc;
    __syncthreads();
    if (wid == 0) {
        float vv = wsum[lane];
#pragma unroll
        for (int o = 1; o < 32; o <<= 1) {
            float n = __shfl_up_sync(0xffffffffu, vv, o);
            if (lane >= o) vv += n;
        }
        wsum[lane] = vv;
    }
    __syncthreads();
    float off = (wid > 0) ? wsum[wid - 1] : 0.f;
    float b1 = off + sc;
    float b0 = b1 - x1;
    g_b[h * S + 2 * tid] = b0;
    g_b[h * S + 2 * tid + 1] = b1;

    float a0 = g_ig[h * S + 2 * tid] - b0;
    float a1 = g_ig[h * S + 2 * tid + 1] - b1;
    g_a[h * S + 2 * tid] = a0;
    g_a[h * S + 2 * tid + 1] = a1;

    float tm = fmaxf(a0, a1);
    float mc = tm;
#pragma unroll
    for (int o = 1; o < 32; o <<= 1) {
        float n = __shfl_up_sync(0xffffffffu, mc, o);
        if (lane >= o) mc = fmaxf(mc, n);
    }
    if (lane == 31) wmax[wid] = mc;
    __syncthreads();
    if (wid == 0) {
        float vv = wmax[lane];
#pragma unroll
        for (int o = 1; o < 32; o <<= 1) {
            float n = __shfl_up_sync(0xffffffffu, vv, o);
            if (lane >= o) vv = fmaxf(vv, n);
        }
        wmax[lane] = vv;
    }
    __syncthreads();
    float moff = (wid > 0) ? wmax[wid - 1] : NEGINF;
    float me = __shfl_up_sync(0xffffffffu, mc, 1);
    if (lane == 0) me = NEGINF;
    float prev = fmaxf(moff, me);
    float M0 = fmaxf(prev, a0);
    float M1 = fmaxf(M0, a1);
    g_M[h * S + 2 * tid] = M0;
    g_M[h * S + 2 * tid + 1] = M1;
}

// ---------------------------------------------------------------------------
// Kernel 3: bf16x2-split (3-product) tensor attention, m16n8k16.
// Block = 64 q-rows x 1 head, 8 warps (wy 2 x wx 4). kv tiles of 64 keys.
// QK warp tile 32x16; PV warp tile 32x32. P aliases K. 2 CTAs/SM.
// bid -> (st,h) mapping pairs co-resident blocks (bid, bid+148) so their
// tile counts sum to 28; the 40 largest (st 27..31) run alone.
// ---------------------------------------------------------------------------
__global__ __launch_bounds__(256, 2) void attn_kernel(
    const float* __restrict__ q, const float* __restrict__ k,
    const float* __restrict__ v)
{
    extern __shared__ unsigned smu[];
    unsigned* Q0 = smu;                    // [64][QSTR] bf16x2 hi
    unsigned* Q1 = Q0 + BS * QSTR;         // lo
    unsigned* K0 = Q1 + BS * QSTR;         // [64][KSTR] hi (aliased by P)
    unsigned* K1 = K0 + BT * KSTR;         // lo
    unsigned* V0 = K1 + BT * KSTR;         // [32][VSTR] key-pair packed hi
    unsigned* V1 = V0 + (BT / 2) * VSTR;   // lo
    float* dss = (float*)(V1 + (BT / 2) * VSTR);   // [64][4]
    unsigned* P0 = K0;                     // [64][PSTR] hi
    unsigned* P1 = K0 + BS * PSTR;         // lo

    // ---- bid -> (st, h): makespan-balanced pairing ----
    int bid = blockIdx.x;
    int st, h;
    if (bid >= 108 && bid < 148) {
        int idx = bid - 108;
        st = 27 + (idx >> 3);
        h = idx & 7;
    } else {
        int p = (bid < 108) ? bid : bid - 148;
        bool first = (bid < 108);
        if (p < 104) {
            st = first ? (26 - (p >> 3)) : (p >> 3);
            h = p & 7;
        } else {
            int qq = p - 104;
            st = 13;
            h = first ? 2 * qq : 2 * qq + 1;
        }
    }
    int s0 = st * BS;

    int tid = threadIdx.x;
    int wid = tid >> 5, lane = tid & 31;
    int g = lane >> 2, tq = lane & 3;
    int wy = wid >> 2, wx = wid & 3;
    const float scale = 0.0883883476483184406f;  // 1/sqrt(128)

    // ---- stage Q (scaled, split, bf16x2 packed) ----
    for (int idx = tid; idx < BS * 32; idx += 256) {
        int r = idx >> 5, c4 = idx & 31;
        float4 qv = *(const float4*)(q + (size_t)(s0 + r) * E + h * DH + 4 * c4);
        unsigned short h0, l0, h1, l1, h2, l2, h3, l3;
        split2(qv.x * scale, h0, l0); split2(qv.y * scale, h1, l1);
        split2(qv.z * scale, h2, l2); split2(qv.w * scale, h3, l3);
        *(uint2*)&Q0[r * QSTR + 2 * c4] = make_uint2(pk(h0, h1), pk(h2, h3));
        *(uint2*)&Q1[r * QSTR + 2 * c4] = make_uint2(pk(l0, l1), pk(l2, l3));
    }

    float Mr[2][2], br[2][2];
#pragma unroll
    for (int mt = 0; mt < 2; mt++)
#pragma unroll
        for (int hf = 0; hf < 2; hf++) {
            int r = s0 + wy * 32 + mt * 16 + hf * 8 + g;
            Mr[mt][hf] = g_M[h * S + r];
            br[mt][hf] = g_b[h * S + r];
        }

    float acc[2][4][4];
#pragma unroll
    for (int mt = 0; mt < 2; mt++)
#pragma unroll
        for (int nt = 0; nt < 4; nt++)
#pragma unroll
            for (int i = 0; i < 4; i++) acc[mt][nt][i] = 0.f;
    float ds[2][2] = {0.f, 0.f, 0.f, 0.f};

    int nT = st + 1;

    for (int t = 0; t < nT; t++) {
        int t0 = t * BT;
        __syncthreads();   // prev PV reads (P,V) done; Q staged (t=0)

        // ---- stage K (split, packed along k) ----
        for (int idx = tid; idx < BT * 32; idx += 256) {
            int r = idx >> 5, c4 = idx & 31;
            float4 kv = *(const float4*)(k + (size_t)(t0 + r) * E + h * DH + 4 * c4);
            unsigned short h0, l0, h1, l1, h2, l2, h3, l3;
            split2(kv.x, h0, l0); split2(kv.y, h1, l1);
            split2(kv.z, h2, l2); split2(kv.w, h3, l3);
            *(uint2*)&K0[r * KSTR + 2 * c4] = make_uint2(pk(h0, h1), pk(h2, h3));
            *(uint2*)&K1[r * KSTR + 2 * c4] = make_uint2(pk(l0, l1), pk(l2, l3));
        }
        // ---- stage V transposed-packed: word = (v[2p][dh], v[2p+1][dh]) ----
        for (int idx = tid; idx < (BT / 2) * DH; idx += 256) {
            int p2 = idx >> 7, dh = idx & 127;
            float f0 = v[(size_t)(t0 + 2 * p2) * E + h * DH + dh];
            float f1 = v[(size_t)(t0 + 2 * p2 + 1) * E + h * DH + dh];
            unsigned short h0, l0, h1, l1;
            split2(f0, h0, l0); split2(f1, h1, l1);
            V0[p2 * VSTR + dh] = pk(h0, h1);
            V1[p2 * VSTR + dh] = pk(l0, l1);
        }
        __syncthreads();

        // ---- QK^T: scores 64x64, warp tile 32x16, 3 bf16 products ----
        float sc[2][2][4];
#pragma unroll
        for (int mt = 0; mt < 2; mt++)
#pragma unroll
            for (int nt = 0; nt < 2; nt++)
#pragma unroll
                for (int i = 0; i < 4; i++) sc[mt][nt][i] = 0.f;

#pragma unroll
        for (int c = 0; c < 8; c++) {
            int co = c * 8 + tq;
            unsigned ah[2][4], al[2][4], bh[2][2], bl[2][2];
#pragma unroll
            for (int mt = 0; mt < 2; mt++) {
                int r0 = wy * 32 + mt * 16 + g;
                ah[mt][0] = Q0[r0 * QSTR + co];
                ah[mt][1] = Q0[(r0 + 8) * QSTR + co];
                ah[mt][2] = Q0[r0 * QSTR + co + 4];
                ah[mt][3] = Q0[(r0 + 8) * QSTR + co + 4];
                al[mt][0] = Q1[r0 * QSTR + co];
                al[mt][1] = Q1[(r0 + 8) * QSTR + co];
                al[mt][2] = Q1[r0 * QSTR + co + 4];
                al[mt][3] = Q1[(r0 + 8) * QSTR + co + 4];
            }
#pragma unroll
            for (int nt = 0; nt < 2; nt++) {
                int key = wx * 16 + nt * 8 + g;
                bh[nt][0] = K0[key * KSTR + co];
                bh[nt][1] = K0[key * KSTR + co + 4];
                bl[nt][0] = K1[key * KSTR + co];
                bl[nt][1] = K1[key * KSTR + co + 4];
            }
#pragma unroll
            for (int mt = 0; mt < 2; mt++)
#pragma unroll
                for (int nt = 0; nt < 2; nt++) {
                    mma16(sc[mt][nt], ah[mt], bh[nt]);
                    mma16(sc[mt][nt], ah[mt], bl[nt]);
                    mma16(sc[mt][nt], al[mt], bh[nt]);
                }
        }
        __syncthreads();   // QK reads of K done before P overwrites

        // ---- decay weights + causal mask; P (split, packed) -> smem ----
        bool lastT = (t == nT - 1);
#pragma unroll
        for (int nt = 0; nt < 2; nt++) {
            int colL = wx * 16 + nt * 8 + 2 * tq;
            int col0 = t0 + colL;
            int colw = (colL >> 1);
            float2 a2 = *(const float2*)&g_a[h * S + col0];
#pragma unroll
            for (int mt = 0; mt < 2; mt++) {
                int r0l = wy * 32 + mt * 16 + g;
                float w0 = __expf(a2.x - Mr[mt][0]);
                float w1 = __expf(a2.y - Mr[mt][0]);
                float w2 = __expf(a2.x - Mr[mt][1]);
                float w3 = __expf(a2.y - Mr[mt][1]);
                if (lastT) {
                    int gr0 = s0 + r0l, gr1 = gr0 + 8;
                    if (col0     > gr0) w0 = 0.f;
                    if (col0 + 1 > gr0) w1 = 0.f;
                    if (col0     > gr1) w2 = 0.f;
                    if (col0 + 1 > gr1) w3 = 0.f;
                }
                float p0 = sc[mt][nt][0] * w0, p1 = sc[mt][nt][1] * w1;
                float p2 = sc[mt][nt][2] * w2, p3 = sc[mt][nt][3] * w3;
                ds[mt][0] += p0 + p1;
                ds[mt][1] += p2 + p3;
                unsigned short h0, l0, h1, l1, h2, l2, h3, l3;
                split2(p0, h0, l0); split2(p1, h1, l1);
                split2(p2, h2, l2); split2(p3, h3, l3);
                P0[r0l * PSTR + colw] = pk(h0, h1);
                P1[r0l * PSTR + colw] = pk(l0, l1);
                P0[(r0l + 8) * PSTR + colw] = pk(h2, h3);
                P1[(r0l + 8) * PSTR + colw] = pk(l2, l3);
            }
        }
        __syncthreads();

        // ---- PV: acc[64x128] += P[64x64] @ V[64x128], 3 bf16 products ----
#pragma unroll
        for (int c = 0; c < 4; c++) {
            int co = c * 8 + tq;
            unsigned ah[2][4], al[2][4], bh[4][2], bl[4][2];
#pragma unroll
            for (int mt = 0; mt < 2; mt++) {
                int r0 = wy * 32 + mt * 16 + g;
                ah[mt][0] = P0[r0 * PSTR + co];
                ah[mt][1] = P0[(r0 + 8) * PSTR + co];
                ah[mt][2] = P0[r0 * PSTR + co + 4];
                ah[mt][3] = P0[(r0 + 8) * PSTR + co + 4];
                al[mt][0] = P1[r0 * PSTR + co];
                al[mt][1] = P1[(r0 + 8) * PSTR + co];
                al[mt][2] = P1[r0 * PSTR + co + 4];
                al[mt][3] = P1[(r0 + 8) * PSTR + co + 4];
            }
#pragma unroll
            for (int nt = 0; nt < 4; nt++) {
                int dh = wx * 32 + nt * 8 + g;
                bh[nt][0] = V0[(c * 8 + tq) * VSTR + dh];
                bh[nt][1] = V0[(c * 8 + tq + 4) * VSTR + dh];
                bl[nt][0] = V1[(c * 8 + tq) * VSTR + dh];
                bl[nt][1] = V1[(c * 8 + tq + 4) * VSTR + dh];
            }
#pragma unroll
            for (int mt = 0; mt < 2; mt++)
#pragma unroll
                for (int nt = 0; nt < 4; nt++) {
                    mma16(acc[mt][nt], ah[mt], bh[nt]);
                    mma16(acc[mt][nt], ah[mt], bl[nt]);
                    mma16(acc[mt][nt], al[mt], bh[nt]);
                }
        }
    }

    // ---- dsum: quad shfl, then cross-warp (wx) via smem ----
#pragma unroll
    for (int mt = 0; mt < 2; mt++)
#pragma unroll
        for (int hf = 0; hf < 2; hf++) {
            float vds = ds[mt][hf];
            vds += __shfl_xor_sync(0xffffffffu, vds, 1);
            vds += __shfl_xor_sync(0xffffffffu, vds, 2);
            if (tq == 0)
                dss[(wy * 32 + mt * 16 + hf * 8 + g) * 4 + wx] = vds;
        }
    __syncthreads();

    // ---- normalize + store ----
#pragma unroll
    for (int mt = 0; mt < 2; mt++) {
        float inv[2];
#pragma unroll
        for (int hf = 0; hf < 2; hf++) {
            int rl = wy * 32 + mt * 16 + hf * 8 + g;
            float tot = dss[rl * 4 + 0] + dss[rl * 4 + 1] +
                        dss[rl * 4 + 2] + dss[rl * 4 + 3];
            float nrm = fmaxf(fabsf(tot), __expf(-(br[mt][hf] + Mr[mt][hf])));
            inv[hf] = 1.f / (nrm + 1e-6f);
        }
#pragma unroll
        for (int nt = 0; nt < 4; nt++) {
            int dh = wx * 32 + nt * 8 + 2 * tq;
            int r0 = s0 + wy * 32 + mt * 16 + g;
            float2 o0 = make_float2(acc[mt][nt][0] * inv[0], acc[mt][nt][1] * inv[0]);
            float2 o1 = make_float2(acc[mt][nt][2] * inv[1], acc[mt][nt][3] * inv[1]);
            *(float2*)&g_h[(size_t)r0 * E + h * DH + dh] = o0;
            *(float2*)&g_h[(size_t)(r0 + 8) * E + h * DH + dh] = o1;
        }
    }
}

// ---------------------------------------------------------------------------
// Kernel 4: residual layer norm (unchanged)
// ---------------------------------------------------------------------------
__global__ __launch_bounds__(256) void ln_kernel(
    const float* __restrict__ lnw, float* __restrict__ out)
{
    int s = blockIdx.x;
    int tid = threadIdx.x;
    int lane = tid & 31, wid = tid >> 5;
    __shared__ float rsum[8], rsq[8];
    __shared__ float s_mu, s_inv;

    float4 hv = ((const float4*)(g_h + (size_t)s * E))[tid];
    float sum = hv.x + hv.y + hv.z + hv.w;
    float sq = hv.x * hv.x + hv.y * hv.y + hv.z * hv.z + hv.w * hv.w;
#pragma unroll
    for (int o = 16; o > 0; o >>= 1) {
        sum += __shfl_xor_sync(0xffffffffu, sum, o);
        sq  += __shfl_xor_sync(0xffffffffu, sq, o);
    }
    if (lane == 0) { rsum[wid] = sum; rsq[wid] = sq; }
    __syncthreads();
    if (tid == 0) {
        float ts = 0.f, tqv = 0.f;
        for (int i = 0; i < 8; i++) { ts += rsum[i]; tqv += rsq[i]; }
        float mu = ts * (1.f / E);
        float var = tqv * (1.f / E) - mu * mu;
        s_mu = mu;
        s_inv = rsqrtf(var + 1e-5f);
    }
    __syncthreads();
    float mu = s_mu, inv = s_inv;

    float4 wv = ((const float4*)lnw)[tid];
    float4 ov;
    ov.x = (hv.x - mu) * inv * (1.f + wv.x);
    ov.y = (hv.y - mu) * inv * (1.f + wv.y);
    ov.z = (hv.z - mu) * inv * (1.f + wv.z);
    ov.w = (hv.w - mu) * inv * (1.f + wv.w);
    ((float4*)(out + (size_t)s * E))[tid] = ov;
}

// ---------------------------------------------------------------------------
extern "C" void kernel_launch(void* const* d_in, const int* in_sizes, int n_in,
                              void* d_out, int out_size)
{
    const float* q   = (const float*)d_in[0];
    const float* k   = (const float*)d_in[1];
    const float* v   = (const float*)d_in[2];
    const float* Wi  = (const float*)d_in[3];
    const float* bi  = (const float*)d_in[4];
    const float* Wf  = (const float*)d_in[5];
    const float* bf  = (const float*)d_in[6];
    const float* lnw = (const float*)d_in[7];
    float* out = (float*)d_out;

    int gates_smem = GR * 3 * E * 4;
    cudaFuncSetAttribute(gates_kernel,
                         cudaFuncAttributeMaxDynamicSharedMemorySize, gates_smem);
    gates_kernel<<<S / GR, 256, gates_smem>>>(q, k, v, Wi, bi, Wf, bf);

    scan_kernel<<<NH, 1024>>>();

    int attn_smem = (2 * BS * QSTR + 2 * BT * KSTR + 2 * (BT / 2) * VSTR) * 4
                    + BS * 4 * 4;
    cudaFuncSetAttribute(attn_kernel,
                         cudaFuncAttributeMaxDynamicSharedMemorySize, attn_smem);
    attn_kernel<<<(S / BS) * NH, 256, attn_smem>>>(q, k, v);

    ln_kernel<<<S, 256>>>(lnw, out);
}

// round 6
// speedup vs baseline: 4.1033x; 1.2420x over previous
#include <cuda_runtime.h>
#include <cuda_bf16.h>
#include <math.h>

#define S 2048
#define E 1024
#define NH 8
#define DH 128
#define BS 64        // q rows per attn block
#define BT 64        // keys per kv tile
#define QSTR 68      // Q/K smem word stride (row = 272B, ldmatrix conflict-free)
#define KSTR 68
#define PSTR 36      // P word stride (144B)
#define VSTR 36      // Vt word stride (144B): 32 key-pair words + pad
#define GR 8         // gate rows per block

// Scratch (allocation-free rule: __device__ globals)
__device__ float g_ig[NH * S];
__device__ float g_logf[NH * S];
__device__ float g_b[NH * S];
__device__ float g_a[NH * S];
__device__ float g_M[NH * S];
__device__ float g_h[(size_t)S * E];
// precomputed bf16 splits (packed 2 per word, along E)
__device__ unsigned g_qhi[S * E / 2];
__device__ unsigned g_qlo[S * E / 2];
__device__ unsigned g_khi[S * E / 2];
__device__ unsigned g_klo[S * E / 2];
// V transposed: [h*DH + dh][S/2] word = (v[2p], v[2p+1]) at that dh
__device__ unsigned g_vthi[NH * DH * (S / 2)];
__device__ unsigned g_vtlo[NH * DH * (S / 2)];

__device__ __forceinline__ float log_sigmoid_f(float x) {
    if (x >= 0.f) return -log1pf(expf(-x));
    return x - log1pf(expf(x));
}

__device__ __forceinline__ unsigned short bfbits(float x) {
    __nv_bfloat16 b = __float2bfloat16_rn(x);
    return *reinterpret_cast<unsigned short*>(&b);
}
__device__ __forceinline__ float bits2f(unsigned short u) {
    __nv_bfloat16 b = *reinterpret_cast<__nv_bfloat16*>(&u);
    return __bfloat162float(b);
}
__device__ __forceinline__ void split2(float x, unsigned short& h, unsigned short& l) {
    h = bfbits(x);
    l = bfbits(x - bits2f(h));
}
__device__ __forceinline__ unsigned pk(unsigned short e0, unsigned short e1) {
    return (unsigned)e0 | ((unsigned)e1 << 16);   // e0 = lower index
}

__device__ __forceinline__ void mma16(float* d, const unsigned* a, const unsigned* b) {
    asm volatile(
        "mma.sync.aligned.m16n8k16.row.col.f32.bf16.bf16.f32 "
        "{%0,%1,%2,%3},{%4,%5,%6,%7},{%8,%9},{%0,%1,%2,%3};"
        : "+f"(d[0]), "+f"(d[1]), "+f"(d[2]), "+f"(d[3])
        : "r"(a[0]), "r"(a[1]), "r"(a[2]), "r"(a[3]), "r"(b[0]), "r"(b[1]));
}

__device__ __forceinline__ void ldsm4(unsigned* r, unsigned saddr) {
    asm volatile("ldmatrix.sync.aligned.m8n8.x4.shared.b16 {%0,%1,%2,%3}, [%4];"
                 : "=r"(r[0]), "=r"(r[1]), "=r"(r[2]), "=r"(r[3]) : "r"(saddr));
}

__device__ __forceinline__ void cpa16(unsigned saddr, const void* g) {
    asm volatile("cp.async.cg.shared.global [%0], [%1], 16;" :: "r"(saddr), "l"(g));
}
__device__ __forceinline__ void cpa_commit() {
    asm volatile("cp.async.commit_group;");
}
__device__ __forceinline__ void cpa_wait0() {
    asm volatile("cp.async.wait_group 0;");
}

// ---------------------------------------------------------------------------
// Kernel 0a: split q (scaled) and k into bf16 hi/lo packed arrays.
// ---------------------------------------------------------------------------
__global__ __launch_bounds__(256) void split_qk_kernel(
    const float* __restrict__ q, const float* __restrict__ k)
{
    size_t i = (size_t)blockIdx.x * 256 + threadIdx.x;   // over S*E/4
    const float scale = 0.0883883476483184406f;
    float4 qv = ((const float4*)q)[i];
    float4 kv = ((const float4*)k)[i];
    unsigned short h0, l0, h1, l1, h2, l2, h3, l3;
    split2(qv.x * scale, h0, l0); split2(qv.y * scale, h1, l1);
    split2(qv.z * scale, h2, l2); split2(qv.w * scale, h3, l3);
    ((uint2*)g_qhi)[i] = make_uint2(pk(h0, h1), pk(h2, h3));
    ((uint2*)g_qlo)[i] = make_uint2(pk(l0, l1), pk(l2, l3));
    split2(kv.x, h0, l0); split2(kv.y, h1, l1);
    split2(kv.z, h2, l2); split2(kv.w, h3, l3);
    ((uint2*)g_khi)[i] = make_uint2(pk(h0, h1), pk(h2, h3));
    ((uint2*)g_klo)[i] = make_uint2(pk(l0, l1), pk(l2, l3));
}

// ---------------------------------------------------------------------------
// Kernel 0b: transpose V per head into [dh][key-pair] bf16 split layout.
// Block = (key chunk of 64, head). smem transpose for coalescing both sides.
// ---------------------------------------------------------------------------
__global__ __launch_bounds__(256) void vt_kernel(const float* __restrict__ v)
{
    __shared__ float vs[64 * 129];
    int c = blockIdx.x;           // key chunk (64 keys)
    int h = blockIdx.y;
    int tid = threadIdx.x;
    for (int idx = tid; idx < 64 * 32; idx += 256) {
        int r = idx >> 5, w = idx & 31;
        float4 f = *(const float4*)(v + (size_t)(c * 64 + r) * E + h * DH + 4 * w);
        vs[r * 129 + 4 * w] = f.x;
        vs[r * 129 + 4 * w + 1] = f.y;
        vs[r * 129 + 4 * w + 2] = f.z;
        vs[r * 129 + 4 * w + 3] = f.w;
    }
    __syncthreads();
    for (int idx = tid; idx < 128 * 32; idx += 256) {
        int dh = idx >> 5, p = idx & 31;
        float f0 = vs[(2 * p) * 129 + dh];
        float f1 = vs[(2 * p + 1) * 129 + dh];
        unsigned short a0, b0, a1, b1;
        split2(f0, a0, b0); split2(f1, a1, b1);
        size_t o = (size_t)(h * DH + dh) * (S / 2) + c * 32 + p;
        g_vthi[o] = pk(a0, a1);
        g_vtlo[o] = pk(b0, b1);
    }
}

// ---------------------------------------------------------------------------
// Kernel 1: gate projections (unchanged)
// ---------------------------------------------------------------------------
__global__ __launch_bounds__(256) void gates_kernel(
    const float* __restrict__ q, const float* __restrict__ k,
    const float* __restrict__ v,
    const float* __restrict__ Wi, const float* __restrict__ bi,
    const float* __restrict__ Wf, const float* __restrict__ bf)
{
    extern __shared__ float gin[];   // [GR][3*E]
    int s0 = blockIdx.x * GR;
    int tid = threadIdx.x;

    for (int idx = tid; idx < GR * (E / 4); idx += 256) {
        int r = idx >> 8;
        int c4 = idx & 255;
        float4* row = (float4*)(gin + r * 3 * E);
        row[c4]       = ((const float4*)(q + (size_t)(s0 + r) * E))[c4];
        row[256 + c4] = ((const float4*)(k + (size_t)(s0 + r) * E))[c4];
        row[512 + c4] = ((const float4*)(v + (size_t)(s0 + r) * E))[c4];
    }
    __syncthreads();

    int w = tid >> 5, lane = tid & 31;
    const float4* wi4 = (const float4*)(Wi + (size_t)w * 3 * E);
    const float4* wf4 = (const float4*)(Wf + (size_t)w * 3 * E);
    float bih = bi[w], bfh = bf[w];

    for (int r = 0; r < GR; r++) {
        const float4* g4 = (const float4*)(gin + r * 3 * E);
        float si = 0.f, sf = 0.f;
        for (int j = lane; j < 3 * E / 4; j += 32) {
            float4 g = g4[j];
            float4 a = wi4[j];
            float4 b = wf4[j];
            si += g.x * a.x + g.y * a.y + g.z * a.z + g.w * a.w;
            sf += g.x * b.x + g.y * b.y + g.z * b.z + g.w * b.w;
        }
#pragma unroll
        for (int o = 16; o > 0; o >>= 1) {
            si += __shfl_xor_sync(0xffffffffu, si, o);
            sf += __shfl_xor_sync(0xffffffffu, sf, o);
        }
        if (lane == 0) {
            g_ig[w * S + s0 + r] = si + bih;
            g_logf[w * S + s0 + r] = log_sigmoid_f(sf + bfh);
        }
    }
}

// ---------------------------------------------------------------------------
// Kernel 2: per-head prefix sum (b) and prefix max (M) (unchanged)
// ---------------------------------------------------------------------------
__global__ __launch_bounds__(1024) void scan_kernel()
{
    __shared__ float wsum[32], wmax[32];
    int h = blockIdx.x, tid = threadIdx.x;
    int lane = tid & 31, wid = tid >> 5;
    const float NEGINF = -3.4e38f;

    float x0 = g_logf[h * S + 2 * tid];
    float x1 = g_logf[h * S + 2 * tid + 1];
    float ts = x0 + x1;

    float sc = ts;
#pragma unroll
    for (int o = 1; o < 32; o <<= 1) {
        float n = __shfl_up_sync(0xffffffffu, sc, o);
        if (lane >= o) sc += n;
    }
    if (lane == 31) wsum[wid] = sc;
    __syncthreads();
    if (wid == 0) {
        float vv = wsum[lane];
#pragma unroll
        for (int o = 1; o < 32; o <<= 1) {
            float n = __shfl_up_sync(0xffffffffu, vv, o);
            if (lane >= o) vv += n;
        }
        wsum[lane] = vv;
    }
    __syncthreads();
    float off = (wid > 0) ? wsum[wid - 1] : 0.f;
    float b1 = off + sc;
    float b0 = b1 - x1;
    g_b[h * S + 2 * tid] = b0;
    g_b[h * S + 2 * tid + 1] = b1;

    float a0 = g_ig[h * S + 2 * tid] - b0;
    float a1 = g_ig[h * S + 2 * tid + 1] - b1;
    g_a[h * S + 2 * tid] = a0;
    g_a[h * S + 2 * tid + 1] = a1;

    float tm = fmaxf(a0, a1);
    float mc = tm;
#pragma unroll
    for (int o = 1; o < 32; o <<= 1) {
        float n = __shfl_up_sync(0xffffffffu, mc, o);
        if (lane >= o) mc = fmaxf(mc, n);
    }
    if (lane == 31) wmax[wid] = mc;
    __syncthreads();
    if (wid == 0) {
        float vv = wmax[lane];
#pragma unroll
        for (int o = 1; o < 32; o <<= 1) {
            float n = __shfl_up_sync(0xffffffffu, vv, o);
            if (lane >= o) vv = fmaxf(vv, n);
        }
        wmax[lane] = vv;
    }
    __syncthreads();
    float moff = (wid > 0) ? wmax[wid - 1] : NEGINF;
    float me = __shfl_up_sync(0xffffffffu, mc, 1);
    if (lane == 0) me = NEGINF;
    float prev = fmaxf(moff, me);
    float M0 = fmaxf(prev, a0);
    float M1 = fmaxf(M0, a1);
    g_M[h * S + 2 * tid] = M0;
    g_M[h * S + 2 * tid + 1] = M1;
}

// ---------------------------------------------------------------------------
// Kernel 3: bf16x2-split tensor attention, ldmatrix + cp.async staging.
// Block = 64 q-rows x 1 head, 8 warps (wy 2 x wx 4). kv tiles of 64 keys.
// QK warp tile 32x16; PV warp tile 32x32. P aliases K. 2 CTAs/SM.
// ---------------------------------------------------------------------------
__global__ __launch_bounds__(256, 2) void attn_kernel()
{
    extern __shared__ unsigned smu[];
    // byte offsets into dynamic smem
    const unsigned Q0o = 0;
    const unsigned Q1o = BS * QSTR * 4;            // 17408
    const unsigned K0o = 2 * Q1o;                  // 34816
    const unsigned K1o = K0o + BT * KSTR * 4;      // 52224
    const unsigned V0o = K1o + BT * KSTR * 4;      // 69632
    const unsigned V1o = V0o + DH * VSTR * 4;      // 88064
    const unsigned DSo = V1o + DH * VSTR * 4;      // 106496
    const unsigned P0o = K0o;
    const unsigned P1o = K0o + BS * PSTR * 4;      // 44032

    unsigned su = (unsigned)__cvta_generic_to_shared(smu);
    unsigned* P0 = smu + P0o / 4;
    unsigned* P1 = smu + P1o / 4;
    float* dss = (float*)(smu + DSo / 4);

    // ---- bid -> (st, h): makespan-balanced pairing ----
    int bid = blockIdx.x;
    int st, h;
    if (bid >= 108 && bid < 148) {
        int idx = bid - 108;
        st = 27 + (idx >> 3);
        h = idx & 7;
    } else {
        int p = (bid < 108) ? bid : bid - 148;
        bool first = (bid < 108);
        if (p < 104) {
            st = first ? (26 - (p >> 3)) : (p >> 3);
            h = p & 7;
        } else {
            int qq = p - 104;
            st = 13;
            h = first ? 2 * qq : 2 * qq + 1;
        }
    }
    int s0 = st * BS;

    int tid = threadIdx.x;
    int wid = tid >> 5, lane = tid & 31;
    int g = lane >> 2, tq = lane & 3;
    int wy = wid >> 2, wx = wid & 3;

    // ---- stage Q via cp.async (joins first tile's commit group) ----
    {
        const uint4* src = (const uint4*)(g_qhi + ((size_t)s0 * E) / 2 + h * 64);
        const uint4* srl = (const uint4*)(g_qlo + ((size_t)s0 * E) / 2 + h * 64);
#pragma unroll
        for (int i = 0; i < 4; i++) {
            int idx = tid + i * 256;          // 1024 total
            int r = idx >> 4, w = idx & 15;
            cpa16(su + Q0o + (r * QSTR + 4 * w) * 4, src + (size_t)r * (E / 8) + w);
            cpa16(su + Q1o + (r * QSTR + 4 * w) * 4, srl + (size_t)r * (E / 8) + w);
        }
    }

    float Mr[2][2], br[2][2];
#pragma unroll
    for (int mt = 0; mt < 2; mt++)
#pragma unroll
        for (int hf = 0; hf < 2; hf++) {
            int r = s0 + wy * 32 + mt * 16 + hf * 8 + g;
            Mr[mt][hf] = g_M[h * S + r];
            br[mt][hf] = g_b[h * S + r];
        }

    float acc[2][4][4];
#pragma unroll
    for (int mt = 0; mt < 2; mt++)
#pragma unroll
        for (int nt = 0; nt < 4; nt++)
#pragma unroll
            for (int i = 0; i < 4; i++) acc[mt][nt][i] = 0.f;
    float ds[2][2] = {0.f, 0.f, 0.f, 0.f};

    // ---- ldmatrix base addresses (per thread) ----
    // A (Q/P): lanes 0-15 rows 0-15, lanes 16-31 same rows at k+8 (4 words)
    int rowA = wy * 32 + (lane & 15);
    int wcA = (lane >> 4) * 4;
    unsigned qa = su + Q0o + (rowA * QSTR + wcA) * 4;
    unsigned pa = su + P0o + (rowA * PSTR + wcA) * 4;
    // B (K): groups: keys {0-7,0-7,8-15,8-15}, k words {0,4,0,4}
    int keyB = wx * 16 + ((lane >> 4) & 1) * 8 + (lane & 7);
    int wkB = ((lane >> 3) & 1) * 4;
    unsigned kb = su + K0o + (keyB * KSTR + wkB) * 4;
    // B (Vt): dh groups of 8, two nt-pairs
    int dhB = wx * 32 + ((lane >> 4) & 1) * 8 + (lane & 7);
    unsigned vb = su + V0o + (dhB * VSTR + wkB) * 4;

    const unsigned DQ = Q1o - Q0o;   // hi->lo delta (Q)
    const unsigned DK = K1o - K0o;
    const unsigned DV = V1o - V0o;
    const unsigned DP = P1o - P0o;

    int nT = st + 1;

    for (int t = 0; t < nT; t++) {
        int t0 = t * BT;
        __syncthreads();   // prev PV reads done; smem free

        // ---- stage K, Vt via cp.async ----
        {
            const uint4* skh = (const uint4*)(g_khi + ((size_t)t0 * E) / 2 + h * 64);
            const uint4* skl = (const uint4*)(g_klo + ((size_t)t0 * E) / 2 + h * 64);
#pragma unroll
            for (int i = 0; i < 4; i++) {
                int idx = tid + i * 256;
                int r = idx >> 4, w = idx & 15;
                cpa16(su + K0o + (r * KSTR + 4 * w) * 4, skh + (size_t)r * (E / 8) + w);
                cpa16(su + K1o + (r * KSTR + 4 * w) * 4, skl + (size_t)r * (E / 8) + w);
            }
            const uint4* svh = (const uint4*)(g_vthi + (size_t)h * DH * (S / 2) + t0 / 2);
            const uint4* svl = (const uint4*)(g_vtlo + (size_t)h * DH * (S / 2) + t0 / 2);
#pragma unroll
            for (int i = 0; i < 4; i++) {
                int idx = tid + i * 256;      // 1024 = 128 dh x 8 uint4
                int dh = idx >> 3, w = idx & 7;
                cpa16(su + V0o + (dh * VSTR + 4 * w) * 4, svh + (size_t)dh * (S / 8) + w);
                cpa16(su + V1o + (dh * VSTR + 4 * w) * 4, svl + (size_t)dh * (S / 8) + w);
            }
        }
        cpa_commit();
        cpa_wait0();
        __syncthreads();

        // ---- QK^T: 64x64 scores, 3 bf16 products ----
        float sc[2][2][4];
#pragma unroll
        for (int mt = 0; mt < 2; mt++)
#pragma unroll
            for (int nt = 0; nt < 2; nt++)
#pragma unroll
                for (int i = 0; i < 4; i++) sc[mt][nt][i] = 0.f;

#pragma unroll
        for (int c = 0; c < 8; c++) {
            unsigned ah[2][4], al[2][4], bh[4], bl[4];
            ldsm4(ah[0], qa + c * 32);
            ldsm4(ah[1], qa + 16 * QSTR * 4 + c * 32);
            ldsm4(al[0], qa + DQ + c * 32);
            ldsm4(al[1], qa + DQ + 16 * QSTR * 4 + c * 32);
            ldsm4(bh, kb + c * 32);
            ldsm4(bl, kb + DK + c * 32);
#pragma unroll
            for (int mt = 0; mt < 2; mt++)
#pragma unroll
                for (int nt = 0; nt < 2; nt++) {
                    mma16(sc[mt][nt], ah[mt], bh + 2 * nt);
                    mma16(sc[mt][nt], ah[mt], bl + 2 * nt);
                    mma16(sc[mt][nt], al[mt], bh + 2 * nt);
                }
        }
        __syncthreads();   // QK reads of K done before P overwrites

        // ---- decay weights + causal mask; P (split, packed) -> smem ----
        bool lastT = (t == nT - 1);
#pragma unroll
        for (int nt = 0; nt < 2; nt++) {
            int colL = wx * 16 + nt * 8 + 2 * tq;
            int col0 = t0 + colL;
            int colw = wx * 8 + nt * 4 + tq;
            float2 a2 = *(const float2*)&g_a[h * S + col0];
#pragma unroll
            for (int mt = 0; mt < 2; mt++) {
                int r0l = wy * 32 + mt * 16 + g;
                float w0 = __expf(a2.x - Mr[mt][0]);
                float w1 = __expf(a2.y - Mr[mt][0]);
                float w2 = __expf(a2.x - Mr[mt][1]);
                float w3 = __expf(a2.y - Mr[mt][1]);
                if (lastT) {
                    int gr0 = s0 + r0l, gr1 = gr0 + 8;
                    if (col0     > gr0) w0 = 0.f;
                    if (col0 + 1 > gr0) w1 = 0.f;
                    if (col0     > gr1) w2 = 0.f;
                    if (col0 + 1 > gr1) w3 = 0.f;
                }
                float p0 = sc[mt][nt][0] * w0, p1 = sc[mt][nt][1] * w1;
                float p2 = sc[mt][nt][2] * w2, p3 = sc[mt][nt][3] * w3;
                ds[mt][0] += p0 + p1;
                ds[mt][1] += p2 + p3;
                unsigned short h0, l0, h1, l1, h2, l2, h3, l3;
                split2(p0, h0, l0); split2(p1, h1, l1);
                split2(p2, h2, l2); split2(p3, h3, l3);
                P0[r0l * PSTR + colw] = pk(h0, h1);
                P1[r0l * PSTR + colw] = pk(l0, l1);
                P0[(r0l + 8) * PSTR + colw] = pk(h2, h3);
                P1[(r0l + 8) * PSTR + colw] = pk(l2, l3);
            }
        }
        __syncthreads();

        // ---- PV: acc[64x128] += P[64x64] @ V[64x128] ----
#pragma unroll
        for (int c = 0; c < 4; c++) {
            unsigned ah[2][4], al[2][4], bh[2][4], bl[2][4];
            ldsm4(ah[0], pa + c * 32);
            ldsm4(ah[1], pa + 16 * PSTR * 4 + c * 32);
            ldsm4(al[0], pa + DP + c * 32);
            ldsm4(al[1], pa + DP + 16 * PSTR * 4 + c * 32);
            ldsm4(bh[0], vb + c * 32);
            ldsm4(bh[1], vb + 16 * VSTR * 4 + c * 32);
            ldsm4(bl[0], vb + DV + c * 32);
            ldsm4(bl[1], vb + DV + 16 * VSTR * 4 + c * 32);
#pragma unroll
            for (int mt = 0; mt < 2; mt++)
#pragma unroll
                for (int nt = 0; nt < 4; nt++) {
                    const unsigned* bhp = bh[nt >> 1] + 2 * (nt & 1);
                    const unsigned* blp = bl[nt >> 1] + 2 * (nt & 1);
                    mma16(acc[mt][nt], ah[mt], bhp);
                    mma16(acc[mt][nt], ah[mt], blp);
                    mma16(acc[mt][nt], al[mt], bhp);
                }
        }
    }

    // ---- dsum: quad shfl, then cross-warp (wx) via smem ----
#pragma unroll
    for (int mt = 0; mt < 2; mt++)
#pragma unroll
        for (int hf = 0; hf < 2; hf++) {
            float vds = ds[mt][hf];
            vds += __shfl_xor_sync(0xffffffffu, vds, 1);
            vds += __shfl_xor_sync(0xffffffffu, vds, 2);
            if (tq == 0)
                dss[(wy * 32 + mt * 16 + hf * 8 + g) * 4 + wx] = vds;
        }
    __syncthreads();

    // ---- normalize + store ----
#pragma unroll
    for (int mt = 0; mt < 2; mt++) {
        float inv[2];
#pragma unroll
        for (int hf = 0; hf < 2; hf++) {
            int rl = wy * 32 + mt * 16 + hf * 8 + g;
            float tot = dss[rl * 4 + 0] + dss[rl * 4 + 1] +
                        dss[rl * 4 + 2] + dss[rl * 4 + 3];
            float nrm = fmaxf(fabsf(tot), __expf(-(br[mt][hf] + Mr[mt][hf])));
            inv[hf] = 1.f / (nrm + 1e-6f);
        }
#pragma unroll
        for (int nt = 0; nt < 4; nt++) {
            int dh = wx * 32 + nt * 8 + 2 * tq;
            int r0 = s0 + wy * 32 + mt * 16 + g;
            float2 o0 = make_float2(acc[mt][nt][0] * inv[0], acc[mt][nt][1] * inv[0]);
            float2 o1 = make_float2(acc[mt][nt][2] * inv[1], acc[mt][nt][3] * inv[1]);
            *(float2*)&g_h[(size_t)r0 * E + h * DH + dh] = o0;
            *(float2*)&g_h[(size_t)(r0 + 8) * E + h * DH + dh] = o1;
        }
    }
}

// ---------------------------------------------------------------------------
// Kernel 4: residual layer norm (unchanged)
// ---------------------------------------------------------------------------
__global__ __launch_bounds__(256) void ln_kernel(
    const float* __restrict__ lnw, float* __restrict__ out)
{
    int s = blockIdx.x;
    int tid = threadIdx.x;
    int lane = tid & 31, wid = tid >> 5;
    __shared__ float rsum[8], rsq[8];
    __shared__ float s_mu, s_inv;

    float4 hv = ((const float4*)(g_h + (size_t)s * E))[tid];
    float sum = hv.x + hv.y + hv.z + hv.w;
    float sq = hv.x * hv.x + hv.y * hv.y + hv.z * hv.z + hv.w * hv.w;
#pragma unroll
    for (int o = 16; o > 0; o >>= 1) {
        sum += __shfl_xor_sync(0xffffffffu, sum, o);
        sq  += __shfl_xor_sync(0xffffffffu, sq, o);
    }
    if (lane == 0) { rsum[wid] = sum; rsq[wid] = sq; }
    __syncthreads();
    if (tid == 0) {
        float ts = 0.f, tqv = 0.f;
        for (int i = 0; i < 8; i++) { ts += rsum[i]; tqv += rsq[i]; }
        float mu = ts * (1.f / E);
        float var = tqv * (1.f / E) - mu * mu;
        s_mu = mu;
        s_inv = rsqrtf(var + 1e-5f);
    }
    __syncthreads();
    float mu = s_mu, inv = s_inv;

    float4 wv = ((const float4*)lnw)[tid];
    float4 ov;
    ov.x = (hv.x - mu) * inv * (1.f + wv.x);
    ov.y = (hv.y - mu) * inv * (1.f + wv.y);
    ov.z = (hv.z - mu) * inv * (1.f + wv.z);
    ov.w = (hv.w - mu) * inv * (1.f + wv.w);
    ((float4*)(out + (size_t)s * E))[tid] = ov;
}

// ---------------------------------------------------------------------------
extern "C" void kernel_launch(void* const* d_in, const int* in_sizes, int n_in,
                              void* d_out, int out_size)
{
    const float* q   = (const float*)d_in[0];
    const float* k   = (const float*)d_in[1];
    const float* v   = (const float*)d_in[2];
    const float* Wi  = (const float*)d_in[3];
    const float* bi  = (const float*)d_in[4];
    const float* Wf  = (const float*)d_in[5];
    const float* bf  = (const float*)d_in[6];
    const float* lnw = (const float*)d_in[7];
    float* out = (float*)d_out;

    split_qk_kernel<<<S * E / 4 / 256, 256>>>(q, k);
    vt_kernel<<<dim3(S / 64, NH), 256>>>(v);

    int gates_smem = GR * 3 * E * 4;
    cudaFuncSetAttribute(gates_kernel,
                         cudaFuncAttributeMaxDynamicSharedMemorySize, gates_smem);
    gates_kernel<<<S / GR, 256, gates_smem>>>(q, k, v, Wi, bi, Wf, bf);

    scan_kernel<<<NH, 1024>>>();

    int attn_smem = (2 * BS * QSTR + 2 * BT * KSTR + 2 * DH * VSTR) * 4 + BS * 4 * 4;
    cudaFuncSetAttribute(attn_kernel,
                         cudaFuncAttributeMaxDynamicSharedMemorySize, attn_smem);
    attn_kernel<<<(S / BS) * NH, 256, attn_smem>>>();

    ln_kernel<<<S, 256>>>(lnw, out);
}

// round 7
// speedup vs baseline: 4.6096x; 1.1234x over previous
#include <cuda_runtime.h>
#include <cuda_bf16.h>
#include <math.h>

#define S 2048
#define E 1024
#define NH 8
#define DH 128
#define BS 64        // q rows per attn block
#define BT 64        // keys per kv tile
#define QSTR 68      // Q/K smem word stride (row = 272B ≡ 16 mod 128: ldmatrix OK)
#define KSTR 68
#define PSTR 36      // P word stride (144B ≡ 16 mod 128)
#define VSTR 36      // Vt word stride (144B)
#define GR 8         // gate rows per block

// ---- attn smem byte offsets (double-buffered K/V, separate P) ----
#define Q0o 0u
#define Q1o 17408u            // DQ
#define KBASE 34816u
#define KBUF 34816u           // one K buffer (hi+lo)
#define DK 17408u
#define VBASE 104448u
#define VBUF 36864u           // one V buffer (hi+lo)
#define DV 18432u
#define P0o 178176u
#define P1o 187392u
#define DP 9216u
#define DSo 196608u
#define SMEM_ATTN 197632u

// Scratch (allocation-free rule: __device__ globals)
__device__ float g_ig[NH * S];
__device__ float g_logf[NH * S];
__device__ float g_b[NH * S];
__device__ float g_a[NH * S];
__device__ float g_M[NH * S];
__device__ float g_h[(size_t)S * E];
// precomputed bf16 splits (packed 2 per word, along E)
__device__ unsigned g_qhi[S * E / 2];
__device__ unsigned g_qlo[S * E / 2];
__device__ unsigned g_khi[S * E / 2];
__device__ unsigned g_klo[S * E / 2];
// V transposed: [h*DH + dh][S/2] word = (v[2p], v[2p+1]) at that dh
__device__ unsigned g_vthi[NH * DH * (S / 2)];
__device__ unsigned g_vtlo[NH * DH * (S / 2)];

__device__ __forceinline__ float log_sigmoid_f(float x) {
    if (x >= 0.f) return -log1pf(expf(-x));
    return x - log1pf(expf(x));
}

__device__ __forceinline__ unsigned short bfbits(float x) {
    __nv_bfloat16 b = __float2bfloat16_rn(x);
    return *reinterpret_cast<unsigned short*>(&b);
}
__device__ __forceinline__ float bits2f(unsigned short u) {
    __nv_bfloat16 b = *reinterpret_cast<__nv_bfloat16*>(&u);
    return __bfloat162float(b);
}
__device__ __forceinline__ void split2(float x, unsigned short& h, unsigned short& l) {
    h = bfbits(x);
    l = bfbits(x - bits2f(h));
}
__device__ __forceinline__ unsigned pk(unsigned short e0, unsigned short e1) {
    return (unsigned)e0 | ((unsigned)e1 << 16);   // e0 = lower index
}
// packed hi-convert of a pair; returns packed word, residuals out
__device__ __forceinline__ unsigned pk2hi(float a, float b, float& ra, float& rb) {
    __nv_bfloat162 hb = __float22bfloat162_rn(make_float2(a, b));
    ra = a - __bfloat162float(hb.x);
    rb = b - __bfloat162float(hb.y);
    return *reinterpret_cast<unsigned*>(&hb);
}
__device__ __forceinline__ unsigned pk2(float a, float b) {
    __nv_bfloat162 hb = __float22bfloat162_rn(make_float2(a, b));
    return *reinterpret_cast<unsigned*>(&hb);
}

__device__ __forceinline__ void mma16(float* d, const unsigned* a, const unsigned* b) {
    asm volatile(
        "mma.sync.aligned.m16n8k16.row.col.f32.bf16.bf16.f32 "
        "{%0,%1,%2,%3},{%4,%5,%6,%7},{%8,%9},{%0,%1,%2,%3};"
        : "+f"(d[0]), "+f"(d[1]), "+f"(d[2]), "+f"(d[3])
        : "r"(a[0]), "r"(a[1]), "r"(a[2]), "r"(a[3]), "r"(b[0]), "r"(b[1]));
}

__device__ __forceinline__ void ldsm4(unsigned* r, unsigned saddr) {
    asm volatile("ldmatrix.sync.aligned.m8n8.x4.shared.b16 {%0,%1,%2,%3}, [%4];"
                 : "=r"(r[0]), "=r"(r[1]), "=r"(r[2]), "=r"(r[3]) : "r"(saddr));
}

__device__ __forceinline__ void cpa16(unsigned saddr, const void* g) {
    asm volatile("cp.async.cg.shared.global [%0], [%1], 16;" :: "r"(saddr), "l"(g));
}
__device__ __forceinline__ void cpa_commit() {
    asm volatile("cp.async.commit_group;");
}
__device__ __forceinline__ void cpa_wait0() {
    asm volatile("cp.async.wait_group 0;");
}

// ---------------------------------------------------------------------------
// Kernel 0a: split q (scaled) and k into bf16 hi/lo packed arrays.
// ---------------------------------------------------------------------------
__global__ __launch_bounds__(256) void split_qk_kernel(
    const float* __restrict__ q, const float* __restrict__ k)
{
    size_t i = (size_t)blockIdx.x * 256 + threadIdx.x;   // over S*E/4
    const float scale = 0.0883883476483184406f;
    float4 qv = ((const float4*)q)[i];
    float4 kv = ((const float4*)k)[i];
    float r0, r1, r2, r3;
    unsigned h01 = pk2hi(qv.x * scale, qv.y * scale, r0, r1);
    unsigned h23 = pk2hi(qv.z * scale, qv.w * scale, r2, r3);
    ((uint2*)g_qhi)[i] = make_uint2(h01, h23);
    ((uint2*)g_qlo)[i] = make_uint2(pk2(r0, r1), pk2(r2, r3));
    h01 = pk2hi(kv.x, kv.y, r0, r1);
    h23 = pk2hi(kv.z, kv.w, r2, r3);
    ((uint2*)g_khi)[i] = make_uint2(h01, h23);
    ((uint2*)g_klo)[i] = make_uint2(pk2(r0, r1), pk2(r2, r3));
}

// ---------------------------------------------------------------------------
// Kernel 0b: transpose V per head into [dh][key-pair] bf16 split layout.
// ---------------------------------------------------------------------------
__global__ __launch_bounds__(256) void vt_kernel(const float* __restrict__ v)
{
    __shared__ float vs[64 * 129];
    int c = blockIdx.x;           // key chunk (64 keys)
    int h = blockIdx.y;
    int tid = threadIdx.x;
    for (int idx = tid; idx < 64 * 32; idx += 256) {
        int r = idx >> 5, w = idx & 31;
        float4 f = *(const float4*)(v + (size_t)(c * 64 + r) * E + h * DH + 4 * w);
        vs[r * 129 + 4 * w] = f.x;
        vs[r * 129 + 4 * w + 1] = f.y;
        vs[r * 129 + 4 * w + 2] = f.z;
        vs[r * 129 + 4 * w + 3] = f.w;
    }
    __syncthreads();
    for (int idx = tid; idx < 128 * 32; idx += 256) {
        int dh = idx >> 5, p = idx & 31;
        float f0 = vs[(2 * p) * 129 + dh];
        float f1 = vs[(2 * p + 1) * 129 + dh];
        float r0, r1;
        unsigned hw = pk2hi(f0, f1, r0, r1);
        size_t o = (size_t)(h * DH + dh) * (S / 2) + c * 32 + p;
        g_vthi[o] = hw;
        g_vtlo[o] = pk2(r0, r1);
    }
}

// ---------------------------------------------------------------------------
// Kernel 1: gate projections (unchanged)
// ---------------------------------------------------------------------------
__global__ __launch_bounds__(256) void gates_kernel(
    const float* __restrict__ q, const float* __restrict__ k,
    const float* __restrict__ v,
    const float* __restrict__ Wi, const float* __restrict__ bi,
    const float* __restrict__ Wf, const float* __restrict__ bf)
{
    extern __shared__ float gin[];   // [GR][3*E]
    int s0 = blockIdx.x * GR;
    int tid = threadIdx.x;

    for (int idx = tid; idx < GR * (E / 4); idx += 256) {
        int r = idx >> 8;
        int c4 = idx & 255;
        float4* row = (float4*)(gin + r * 3 * E);
        row[c4]       = ((const float4*)(q + (size_t)(s0 + r) * E))[c4];
        row[256 + c4] = ((const float4*)(k + (size_t)(s0 + r) * E))[c4];
        row[512 + c4] = ((const float4*)(v + (size_t)(s0 + r) * E))[c4];
    }
    __syncthreads();

    int w = tid >> 5, lane = tid & 31;
    const float4* wi4 = (const float4*)(Wi + (size_t)w * 3 * E);
    const float4* wf4 = (const float4*)(Wf + (size_t)w * 3 * E);
    float bih = bi[w], bfh = bf[w];

    for (int r = 0; r < GR; r++) {
        const float4* g4 = (const float4*)(gin + r * 3 * E);
        float si = 0.f, sf = 0.f;
        for (int j = lane; j < 3 * E / 4; j += 32) {
            float4 g = g4[j];
            float4 a = wi4[j];
            float4 b = wf4[j];
            si += g.x * a.x + g.y * a.y + g.z * a.z + g.w * a.w;
            sf += g.x * b.x + g.y * b.y + g.z * b.z + g.w * b.w;
        }
#pragma unroll
        for (int o = 16; o > 0; o >>= 1) {
            si += __shfl_xor_sync(0xffffffffu, si, o);
            sf += __shfl_xor_sync(0xffffffffu, sf, o);
        }
        if (lane == 0) {
            g_ig[w * S + s0 + r] = si + bih;
            g_logf[w * S + s0 + r] = log_sigmoid_f(sf + bfh);
        }
    }
}

// ---------------------------------------------------------------------------
// Kernel 2: per-head prefix sum (b) and prefix max (M) (unchanged)
// ---------------------------------------------------------------------------
__global__ __launch_bounds__(1024) void scan_kernel()
{
    __shared__ float wsum[32], wmax[32];
    int h = blockIdx.x, tid = threadIdx.x;
    int lane = tid & 31, wid = tid >> 5;
    const float NEGINF = -3.4e38f;

    float x0 = g_logf[h * S + 2 * tid];
    float x1 = g_logf[h * S + 2 * tid + 1];
    float ts = x0 + x1;

    float sc = ts;
#pragma unroll
    for (int o = 1; o < 32; o <<= 1) {
        float n = __shfl_up_sync(0xffffffffu, sc, o);
        if (lane >= o) sc += n;
    }
    if (lane == 31) wsum[wid] = sc;
    __syncthreads();
    if (wid == 0) {
        float vv = wsum[lane];
#pragma unroll
        for (int o = 1; o < 32; o <<= 1) {
            float n = __shfl_up_sync(0xffffffffu, vv, o);
            if (lane >= o) vv += n;
        }
        wsum[lane] = vv;
    }
    __syncthreads();
    float off = (wid > 0) ? wsum[wid - 1] : 0.f;
    float b1 = off + sc;
    float b0 = b1 - x1;
    g_b[h * S + 2 * tid] = b0;
    g_b[h * S + 2 * tid + 1] = b1;

    float a0 = g_ig[h * S + 2 * tid] - b0;
    float a1 = g_ig[h * S + 2 * tid + 1] - b1;
    g_a[h * S + 2 * tid] = a0;
    g_a[h * S + 2 * tid + 1] = a1;

    float tm = fmaxf(a0, a1);
    float mc = tm;
#pragma unroll
    for (int o = 1; o < 32; o <<= 1) {
        float n = __shfl_up_sync(0xffffffffu, mc, o);
        if (lane >= o) mc = fmaxf(mc, n);
    }
    if (lane == 31) wmax[wid] = mc;
    __syncthreads();
    if (wid == 0) {
        float vv = wmax[lane];
#pragma unroll
        for (int o = 1; o < 32; o <<= 1) {
            float n = __shfl_up_sync(0xffffffffu, vv, o);
            if (lane >= o) vv = fmaxf(vv, n);
        }
        wmax[lane] = vv;
    }
    __syncthreads();
    float moff = (wid > 0) ? wmax[wid - 1] : NEGINF;
    float me = __shfl_up_sync(0xffffffffu, mc, 1);
    if (lane == 0) me = NEGINF;
    float prev = fmaxf(moff, me);
    float M0 = fmaxf(prev, a0);
    float M1 = fmaxf(M0, a1);
    g_M[h * S + 2 * tid] = M0;
    g_M[h * S + 2 * tid + 1] = M1;
}

// ---------------------------------------------------------------------------
// Kernel 3: bf16x2-split tensor attention, double-buffered cp.async pipeline.
// Block = 64 q-rows x 1 head, 8 warps (wy 2 x wx 4). kv tiles of 64 keys.
// Separate P buffer -> 2 syncthreads per tile, staging fully overlapped.
// 1 CTA/SM (193 KB smem).
// ---------------------------------------------------------------------------
__global__ __launch_bounds__(256, 1) void attn_kernel()
{
    extern __shared__ unsigned smu[];
    unsigned su = (unsigned)__cvta_generic_to_shared(smu);
    unsigned* P0 = smu + P0o / 4;
    unsigned* P1 = smu + P1o / 4;
    float* dss = (float*)(smu + DSo / 4);

    // ---- bid -> (st, h): makespan-balanced pairing (bid, bid+148 sum 28) ----
    int bid = blockIdx.x;
    int st, h;
    if (bid >= 108 && bid < 148) {
        int idx = bid - 108;
        st = 27 + (idx >> 3);
        h = idx & 7;
    } else {
        int p = (bid < 108) ? bid : bid - 148;
        bool first = (bid < 108);
        if (p < 104) {
            st = first ? (26 - (p >> 3)) : (p >> 3);
            h = p & 7;
        } else {
            int qq = p - 104;
            st = 13;
            h = first ? 2 * qq : 2 * qq + 1;
        }
    }
    int s0 = st * BS;

    int tid = threadIdx.x;
    int wid = tid >> 5, lane = tid & 31;
    int g = lane >> 2, tq = lane & 3;
    int wy = wid >> 2, wx = wid & 3;

    // ---- staging helper: K,Vt tile t -> buffer b ----
    auto stage_kv = [&](int t, int b) {
        int t0 = t * BT;
        const uint4* skh = (const uint4*)(g_khi + ((size_t)t0 * E) / 2 + h * 64);
        const uint4* skl = (const uint4*)(g_klo + ((size_t)t0 * E) / 2 + h * 64);
        unsigned kdst = su + KBASE + (unsigned)b * KBUF;
#pragma unroll
        for (int i = 0; i < 4; i++) {
            int idx = tid + i * 256;
            int r = idx >> 4, w = idx & 15;
            unsigned o = (r * KSTR + 4 * w) * 4;
            cpa16(kdst + o, skh + (size_t)r * (E / 8) + w);
            cpa16(kdst + DK + o, skl + (size_t)r * (E / 8) + w);
        }
        const uint4* svh = (const uint4*)(g_vthi + (size_t)h * DH * (S / 2) + t0 / 2);
        const uint4* svl = (const uint4*)(g_vtlo + (size_t)h * DH * (S / 2) + t0 / 2);
        unsigned vdst = su + VBASE + (unsigned)b * VBUF;
#pragma unroll
        for (int i = 0; i < 4; i++) {
            int idx = tid + i * 256;
            int dh = idx >> 3, w = idx & 7;
            unsigned o = (dh * VSTR + 4 * w) * 4;
            cpa16(vdst + o, svh + (size_t)dh * (S / 8) + w);
            cpa16(vdst + DV + o, svl + (size_t)dh * (S / 8) + w);
        }
    };

    // ---- stage Q + tile 0 (one group) ----
    {
        const uint4* sqh = (const uint4*)(g_qhi + ((size_t)s0 * E) / 2 + h * 64);
        const uint4* sql = (const uint4*)(g_qlo + ((size_t)s0 * E) / 2 + h * 64);
#pragma unroll
        for (int i = 0; i < 4; i++) {
            int idx = tid + i * 256;
            int r = idx >> 4, w = idx & 15;
            unsigned o = (r * QSTR + 4 * w) * 4;
            cpa16(su + Q0o + o, sqh + (size_t)r * (E / 8) + w);
            cpa16(su + Q1o + o, sql + (size_t)r * (E / 8) + w);
        }
    }
    stage_kv(0, 0);
    cpa_commit();

    float Mr[2][2], br[2][2];
#pragma unroll
    for (int mt = 0; mt < 2; mt++)
#pragma unroll
        for (int hf = 0; hf < 2; hf++) {
            int r = s0 + wy * 32 + mt * 16 + hf * 8 + g;
            Mr[mt][hf] = g_M[h * S + r];
            br[mt][hf] = g_b[h * S + r];
        }

    float acc[2][4][4];
#pragma unroll
    for (int mt = 0; mt < 2; mt++)
#pragma unroll
        for (int nt = 0; nt < 4; nt++)
#pragma unroll
            for (int i = 0; i < 4; i++) acc[mt][nt][i] = 0.f;
    float ds[2][2] = {0.f, 0.f, 0.f, 0.f};

    // ---- ldmatrix per-thread offsets ----
    int rowA = wy * 32 + (lane & 15);
    int wcA = (lane >> 4) * 4;
    unsigned qa = su + Q0o + (rowA * QSTR + wcA) * 4;
    unsigned pa = su + P0o + (rowA * PSTR + wcA) * 4;
    int keyB = wx * 16 + ((lane >> 4) & 1) * 8 + (lane & 7);
    int wkB = ((lane >> 3) & 1) * 4;
    unsigned koff = (keyB * KSTR + wkB) * 4;
    int dhB = wx * 32 + ((lane >> 4) & 1) * 8 + (lane & 7);
    unsigned voff = (dhB * VSTR + wkB) * 4;

    int nT = st + 1;

    for (int t = 0; t < nT; t++) {
        int b = t & 1;
        unsigned kb = su + KBASE + (unsigned)b * KBUF + koff;
        unsigned vb = su + VBASE + (unsigned)b * VBUF + voff;

        cpa_wait0();       // tile t data landed (only pending group)
        __syncthreads();   // visible to all; prev PV done with buffer 1-b and P

        if (t + 1 < nT) {  // prefetch next tile into the free buffer
            stage_kv(t + 1, 1 - b);
            cpa_commit();
        }

        // ---- QK^T: 64x64 scores, 3 bf16 products ----
        float sc[2][2][4];
#pragma unroll
        for (int mt = 0; mt < 2; mt++)
#pragma unroll
            for (int nt = 0; nt < 2; nt++)
#pragma unroll
                for (int i = 0; i < 4; i++) sc[mt][nt][i] = 0.f;

#pragma unroll
        for (int c = 0; c < 8; c++) {
            unsigned ah[2][4], al[2][4], bh[4], bl[4];
            ldsm4(ah[0], qa + c * 32);
            ldsm4(ah[1], qa + 16 * QSTR * 4 + c * 32);
            ldsm4(al[0], qa + Q1o - Q0o + c * 32);
            ldsm4(al[1], qa + Q1o - Q0o + 16 * QSTR * 4 + c * 32);
            ldsm4(bh, kb + c * 32);
            ldsm4(bl, kb + DK + c * 32);
#pragma unroll
            for (int mt = 0; mt < 2; mt++)
#pragma unroll
                for (int nt = 0; nt < 2; nt++) {
                    mma16(sc[mt][nt], ah[mt], bh + 2 * nt);
                    mma16(sc[mt][nt], ah[mt], bl + 2 * nt);
                    mma16(sc[mt][nt], al[mt], bh + 2 * nt);
                }
        }

        // ---- decay weights + causal mask; P (split, packed) -> smem ----
        int t0 = t * BT;
        bool lastT = (t == nT - 1);
#pragma unroll
        for (int nt = 0; nt < 2; nt++) {
            int colL = wx * 16 + nt * 8 + 2 * tq;
            int col0 = t0 + colL;
            int colw = wx * 8 + nt * 4 + tq;
            float2 a2 = *(const float2*)&g_a[h * S + col0];
#pragma unroll
            for (int mt = 0; mt < 2; mt++) {
                int r0l = wy * 32 + mt * 16 + g;
                float w0 = __expf(a2.x - Mr[mt][0]);
                float w1 = __expf(a2.y - Mr[mt][0]);
                float w2 = __expf(a2.x - Mr[mt][1]);
                float w3 = __expf(a2.y - Mr[mt][1]);
                if (lastT) {
                    int gr0 = s0 + r0l, gr1 = gr0 + 8;
                    if (col0     > gr0) w0 = 0.f;
                    if (col0 + 1 > gr0) w1 = 0.f;
                    if (col0     > gr1) w2 = 0.f;
                    if (col0 + 1 > gr1) w3 = 0.f;
                }
                float p0 = sc[mt][nt][0] * w0, p1 = sc[mt][nt][1] * w1;
                float p2 = sc[mt][nt][2] * w2, p3 = sc[mt][nt][3] * w3;
                ds[mt][0] += p0 + p1;
                ds[mt][1] += p2 + p3;
                float r0, r1, r2, r3;
                unsigned uh0 = pk2hi(p0, p1, r0, r1);
                unsigned uh1 = pk2hi(p2, p3, r2, r3);
                P0[r0l * PSTR + colw] = uh0;
                P1[r0l * PSTR + colw] = pk2(r0, r1);
                P0[(r0l + 8) * PSTR + colw] = uh1;
                P1[(r0l + 8) * PSTR + colw] = pk2(r2, r3);
            }
        }
        __syncthreads();   // P visible to all warps

        // ---- PV: acc[64x128] += P[64x64] @ V[64x128] ----
#pragma unroll
        for (int c = 0; c < 4; c++) {
            unsigned ah[2][4], al[2][4], bh[2][4], bl[2][4];
            ldsm4(ah[0], pa + c * 32);
            ldsm4(ah[1], pa + 16 * PSTR * 4 + c * 32);
            ldsm4(al[0], pa + DP + c * 32);
            ldsm4(al[1], pa + DP + 16 * PSTR * 4 + c * 32);
            ldsm4(bh[0], vb + c * 32);
            ldsm4(bh[1], vb + 16 * VSTR * 4 + c * 32);
            ldsm4(bl[0], vb + DV + c * 32);
            ldsm4(bl[1], vb + DV + 16 * VSTR * 4 + c * 32);
#pragma unroll
            for (int mt = 0; mt < 2; mt++)
#pragma unroll
                for (int nt = 0; nt < 4; nt++) {
                    const unsigned* bhp = bh[nt >> 1] + 2 * (nt & 1);
                    const unsigned* blp = bl[nt >> 1] + 2 * (nt & 1);
                    mma16(acc[mt][nt], ah[mt], bhp);
                    mma16(acc[mt][nt], ah[mt], blp);
                    mma16(acc[mt][nt], al[mt], bhp);
                }
        }
    }

    // ---- dsum: quad shfl, then cross-warp (wx) via smem ----
#pragma unroll
    for (int mt = 0; mt < 2; mt++)
#pragma unroll
        for (int hf = 0; hf < 2; hf++) {
            float vds = ds[mt][hf];
            vds += __shfl_xor_sync(0xffffffffu, vds, 1);
            vds += __shfl_xor_sync(0xffffffffu, vds, 2);
            if (tq == 0)
                dss[(wy * 32 + mt * 16 + hf * 8 + g) * 4 + wx] = vds;
        }
    __syncthreads();

    // ---- normalize + store ----
#pragma unroll
    for (int mt = 0; mt < 2; mt++) {
        float inv[2];
#pragma unroll
        for (int hf = 0; hf < 2; hf++) {
            int rl = wy * 32 + mt * 16 + hf * 8 + g;
            float tot = dss[rl * 4 + 0] + dss[rl * 4 + 1] +
                        dss[rl * 4 + 2] + dss[rl * 4 + 3];
            float nrm = fmaxf(fabsf(tot), __expf(-(br[mt][hf] + Mr[mt][hf])));
            inv[hf] = 1.f / (nrm + 1e-6f);
        }
#pragma unroll
        for (int nt = 0; nt < 4; nt++) {
            int dh = wx * 32 + nt * 8 + 2 * tq;
            int r0 = s0 + wy * 32 + mt * 16 + g;
            float2 o0 = make_float2(acc[mt][nt][0] * inv[0], acc[mt][nt][1] * inv[0]);
            float2 o1 = make_float2(acc[mt][nt][2] * inv[1], acc[mt][nt][3] * inv[1]);
            *(float2*)&g_h[(size_t)r0 * E + h * DH + dh] = o0;
            *(float2*)&g_h[(size_t)(r0 + 8) * E + h * DH + dh] = o1;
        }
    }
}

// ---------------------------------------------------------------------------
// Kernel 4: residual layer norm (unchanged)
// ---------------------------------------------------------------------------
__global__ __launch_bounds__(256) void ln_kernel(
    const float* __restrict__ lnw, float* __restrict__ out)
{
    int s = blockIdx.x;
    int tid = threadIdx.x;
    int lane = tid & 31, wid = tid >> 5;
    __shared__ float rsum[8], rsq[8];
    __shared__ float s_mu, s_inv;

    float4 hv = ((const float4*)(g_h + (size_t)s * E))[tid];
    float sum = hv.x + hv.y + hv.z + hv.w;
    float sq = hv.x * hv.x + hv.y * hv.y + hv.z * hv.z + hv.w * hv.w;
#pragma unroll
    for (int o = 16; o > 0; o >>= 1) {
        sum += __shfl_xor_sync(0xffffffffu, sum, o);
        sq  += __shfl_xor_sync(0xffffffffu, sq, o);
    }
    if (lane == 0) { rsum[wid] = sum; rsq[wid] = sq; }
    __syncthreads();
    if (tid == 0) {
        float ts = 0.f, tqv = 0.f;
        for (int i = 0; i < 8; i++) { ts += rsum[i]; tqv += rsq[i]; }
        float mu = ts * (1.f / E);
        float var = tqv * (1.f / E) - mu * mu;
        s_mu = mu;
        s_inv = rsqrtf(var + 1e-5f);
    }
    __syncthreads();
    float mu = s_mu, inv = s_inv;

    float4 wv = ((const float4*)lnw)[tid];
    float4 ov;
    ov.x = (hv.x - mu) * inv * (1.f + wv.x);
    ov.y = (hv.y - mu) * inv * (1.f + wv.y);
    ov.z = (hv.z - mu) * inv * (1.f + wv.z);
    ov.w = (hv.w - mu) * inv * (1.f + wv.w);
    ((float4*)(out + (size_t)s * E))[tid] = ov;
}

// ---------------------------------------------------------------------------
extern "C" void kernel_launch(void* const* d_in, const int* in_sizes, int n_in,
                              void* d_out, int out_size)
{
    const float* q   = (const float*)d_in[0];
    const float* k   = (const float*)d_in[1];
    const float* v   = (const float*)d_in[2];
    const float* Wi  = (const float*)d_in[3];
    const float* bi  = (const float*)d_in[4];
    const float* Wf  = (const float*)d_in[5];
    const float* bf  = (const float*)d_in[6];
    const float* lnw = (const float*)d_in[7];
    float* out = (float*)d_out;

    split_qk_kernel<<<S * E / 4 / 256, 256>>>(q, k);
    vt_kernel<<<dim3(S / 64, NH), 256>>>(v);

    int gates_smem = GR * 3 * E * 4;
    cudaFuncSetAttribute(gates_kernel,
                         cudaFuncAttributeMaxDynamicSharedMemorySize, gates_smem);
    gates_kernel<<<S / GR, 256, gates_smem>>>(q, k, v, Wi, bi, Wf, bf);

    scan_kernel<<<NH, 1024>>>();

    cudaFuncSetAttribute(attn_kernel,
                         cudaFuncAttributeMaxDynamicSharedMemorySize, SMEM_ATTN);
    attn_kernel<<<(S / BS) * NH, 256, SMEM_ATTN>>>();

    ln_kernel<<<S, 256>>>(lnw, out);
}